// round 7
// baseline (speedup 1.0000x reference)
#include <cuda_runtime.h>
#include <math.h>

#define HD 256
#define DD 64

__device__ float g_W1T[2 * DD * HD];   // [pass][(j*64 + m)]
__device__ float g_W2T[2 * HD * HD];   // [pass][(k*256 + j)]

__global__ void prep_kernel(const float* __restrict__ W1m, const float* __restrict__ W2m,
                            const float* __restrict__ W1q, const float* __restrict__ W2q)
{
    int t = blockIdx.x * blockDim.x + threadIdx.x;
    if (t < DD * HD) {
        int j = t >> 6, m = t & 63;
        g_W1T[t]           = W1m[m * HD + j];
        g_W1T[DD * HD + t] = W1q[m * HD + j];
    }
    if (t < HD * HD) {
        int k = t >> 8, j = t & 255;
        g_W2T[t]           = W2m[j * HD + k];
        g_W2T[HD * HD + t] = W2q[j * HD + k];
    }
}

// Shared memory (floats), NS=2 samples per CTA:
//   Mt  [128][68]  8704  (M k-tile, PITCH 68: multiple of 4 for float4 alignment;
//                         reused as H-reduction buffer and Sv)
//   Bs  1024  (8j x 128k W2 tile)
//   Ast  512  (8j x 64m scaled W1T tile)
//   Hs  4352  (2 x 32x68)
//   vA/vB/vC/vD/vE 512 each: h1->aus | ccs->gpart | aas | sss->dds | ees
//   xs 128, gsA 128
#define SMEM_FLOATS (8704 + 1024 + 512 + 4352 + 5*512 + 128 + 128)
#define SMEM_BYTES  (SMEM_FLOATS * 4)

__global__ __launch_bounds__(256, 3)
void lnn_kernel(const float* __restrict__ x,
                const float* __restrict__ W1m, const float* __restrict__ b1m,
                const float* __restrict__ W2m, const float* __restrict__ b2m,
                const float* __restrict__ W3m,
                const float* __restrict__ W1q, const float* __restrict__ b1q,
                const float* __restrict__ W2q, const float* __restrict__ b2q,
                const float* __restrict__ W3q,
                float* __restrict__ out)
{
    extern __shared__ float sm[];
    float* Mt  = sm;              // 8704 (pitch 68)
    float* Bs  = Mt + 8704;       // 1024
    float* Ast = Bs + 1024;       // 512
    float* Hs  = Ast + 512;       // 4352
    float* vA  = Hs + 4352;       // 512  h1 pair -> aus pair
    float* vB  = vA + 512;        // 512  ccs pair -> gpart pair
    float* vC  = vB + 512;        // 512  aas pair
    float* vD  = vC + 512;        // 512  sss pair -> dds pair
    float* vE  = vD + 512;        // 512  ees pair
    float* xs  = vE + 512;        // 128
    float* gsA = xs + 128;        // 128

    const int tid = threadIdx.x;
    const int b   = blockIdx.x;   // handles samples 2b, 2b+1

    for (int q = tid; q < 4352; q += 256) Hs[q] = 0.0f;
    if (tid < 128) { gsA[tid] = 0.0f; xs[tid] = x[b * 128 + tid]; }
    __syncthreads();

    #pragma unroll 1
    for (int pass = 0; pass < 2; pass++) {
        const float* W1  = pass ? W1q : W1m;
        const float* b1  = pass ? b1q : b1m;
        const float* W2  = pass ? W2q : W2m;
        const float* b2  = pass ? b2q : b2m;
        const float* W3  = pass ? W3q : W3m;
        const float* W1T = g_W1T + pass * (DD * HD);
        const float* W2T = g_W2T + pass * (HD * HD);

        // ---- Stage 1: z1 = x W1 + b1 (both samples); h1, a, s ----
        {
            int j = tid;
            float bv = b1[j];
            float p0 = bv, p1 = 0.f, p2 = 0.f, p3 = 0.f;
            float q0 = bv, q1 = 0.f, q2 = 0.f, q3 = 0.f;
            const float4* x0 = (const float4*)xs;
            const float4* x1 = (const float4*)(xs + 64);
            #pragma unroll 4
            for (int i4 = 0; i4 < 16; i4++) {
                int i = i4 * 4;
                float w0 = W1[(i + 0) * HD + j];
                float w1 = W1[(i + 1) * HD + j];
                float w2 = W1[(i + 2) * HD + j];
                float w3 = W1[(i + 3) * HD + j];
                float4 u0 = x0[i4], u1 = x1[i4];
                p0 = fmaf(u0.x, w0, p0); q0 = fmaf(u1.x, w0, q0);
                p1 = fmaf(u0.y, w1, p1); q1 = fmaf(u1.y, w1, q1);
                p2 = fmaf(u0.z, w2, p2); q2 = fmaf(u1.z, w2, q2);
                p3 = fmaf(u0.w, w3, p3); q3 = fmaf(u1.w, w3, q3);
            }
            float z0 = (p0 + p1) + (p2 + p3);
            float z1 = (q0 + q1) + (q2 + q3);
            #pragma unroll
            for (int ns = 0; ns < 2; ns++) {
                float z = ns ? z1 : z0;
                float h, a, s;
                if (pass == 0) {
                    float sg = 1.0f / (1.0f + __expf(-z));
                    h = fmaxf(z, 0.0f) + log1pf(__expf(-fabsf(z)));
                    a = sg;
                    s = sg * (1.0f - sg);
                } else {
                    float t = tanhf(0.5f * z);
                    float o = 1.0f - t * t;
                    h = z * t;
                    a = fmaf(0.5f * z, o, t);
                    s = o * (1.0f - 0.5f * z * t);
                }
                vA[ns * 256 + j] = h;   // h1
                vC[ns * 256 + j] = a;   // aas
                vD[ns * 256 + j] = s;   // sss (becomes dds in stage 3)
            }
        }
        __syncthreads();

        // ---- Stage 2: z2 = h1 W2 + b2 (both samples); c = act'*w3, e = act''*w3 ----
        {
            int k = tid;
            float bv = b2[k];
            float p0 = bv, p1 = 0.f, p2 = 0.f, p3 = 0.f;
            float q0 = bv, q1 = 0.f, q2 = 0.f, q3 = 0.f;
            const float4* h0 = (const float4*)vA;
            const float4* h1 = (const float4*)(vA + 256);
            #pragma unroll 4
            for (int l4 = 0; l4 < 64; l4++) {
                int l = l4 * 4;
                float w0 = W2[(l + 0) * HD + k];
                float w1 = W2[(l + 1) * HD + k];
                float w2 = W2[(l + 2) * HD + k];
                float w3 = W2[(l + 3) * HD + k];
                float4 u0 = h0[l4], u1 = h1[l4];
                p0 = fmaf(u0.x, w0, p0); q0 = fmaf(u1.x, w0, q0);
                p1 = fmaf(u0.y, w1, p1); q1 = fmaf(u1.y, w1, q1);
                p2 = fmaf(u0.z, w2, p2); q2 = fmaf(u1.z, w2, q2);
                p3 = fmaf(u0.w, w3, p3); q3 = fmaf(u1.w, w3, q3);
            }
            float z0 = (p0 + p1) + (p2 + p3);
            float z1 = (q0 + q1) + (q2 + q3);
            float w3v = W3[k];
            #pragma unroll
            for (int ns = 0; ns < 2; ns++) {
                float z = ns ? z1 : z0;
                float a, s;
                if (pass == 0) {
                    float sg = 1.0f / (1.0f + __expf(-z));
                    a = sg;
                    s = sg * (1.0f - sg);
                } else {
                    float t = tanhf(0.5f * z);
                    float o = 1.0f - t * t;
                    a = fmaf(0.5f * z, o, t);
                    s = o * (1.0f - 0.5f * z * t);
                }
                vB[ns * 256 + k] = a * w3v;   // ccs
                vE[ns * 256 + k] = s * w3v;   // ees
            }
        }
        __syncthreads();

        // ---- Stage 3: u = W2 c (both samples); dds = sss*u, aus = aas*u ----
        {
            int j = tid;
            float p0 = 0.f, p1 = 0.f, p2 = 0.f, p3 = 0.f;
            float q0 = 0.f, q1 = 0.f, q2 = 0.f, q3 = 0.f;
            const float4* c0 = (const float4*)vB;
            const float4* c1 = (const float4*)(vB + 256);
            #pragma unroll 4
            for (int k4 = 0; k4 < 64; k4++) {
                int k = k4 * 4;
                float w0 = W2T[(k + 0) * HD + j];
                float w1 = W2T[(k + 1) * HD + j];
                float w2 = W2T[(k + 2) * HD + j];
                float w3 = W2T[(k + 3) * HD + j];
                float4 u0 = c0[k4], u1 = c1[k4];
                p0 = fmaf(u0.x, w0, p0); q0 = fmaf(u1.x, w0, q0);
                p1 = fmaf(u0.y, w1, p1); q1 = fmaf(u1.y, w1, q1);
                p2 = fmaf(u0.z, w2, p2); q2 = fmaf(u1.z, w2, q2);
                p3 = fmaf(u0.w, w3, p3); q3 = fmaf(u1.w, w3, q3);
            }
            float u0v = (p0 + p1) + (p2 + p3);
            float u1v = (q0 + q1) + (q2 + q3);
            float s0 = vD[j], s1 = vD[256 + j];
            float a0 = vC[j], a1 = vC[256 + j];
            vD[j]       = s0 * u0v;  vD[256 + j] = s1 * u1v;   // dds
            vA[j]       = a0 * u0v;  vA[256 + j] = a1 * u1v;   // aus (h1 dead)
        }
        __syncthreads();

        // ---- Stage 4: g = W1 (a*u) (both samples), 4-way j-split ----
        {
            int m = tid & 63, part = tid >> 6;
            const float* W1Tp = W1T + part * 64 * 64;
            const float4* a0 = (const float4*)(vA + part * 64);
            const float4* a1 = (const float4*)(vA + 256 + part * 64);
            float p0 = 0.f, p1 = 0.f, p2 = 0.f, p3 = 0.f;
            float q0 = 0.f, q1 = 0.f, q2 = 0.f, q3 = 0.f;
            #pragma unroll 4
            for (int j4 = 0; j4 < 16; j4++) {
                int jj = j4 * 4;
                float w0 = W1Tp[(jj + 0) * 64 + m];
                float w1 = W1Tp[(jj + 1) * 64 + m];
                float w2 = W1Tp[(jj + 2) * 64 + m];
                float w3 = W1Tp[(jj + 3) * 64 + m];
                float4 u0 = a0[j4], u1 = a1[j4];
                p0 = fmaf(w0, u0.x, p0); q0 = fmaf(w0, u1.x, q0);
                p1 = fmaf(w1, u0.y, p1); q1 = fmaf(w1, u1.y, q1);
                p2 = fmaf(w2, u0.z, p2); q2 = fmaf(w2, u1.z, q2);
                p3 = fmaf(w3, u0.w, p3); q3 = fmaf(w3, u1.w, q3);
            }
            float g0 = (p0 + p1) + (p2 + p3);
            float g1 = (q0 + q1) + (q2 + q3);
            __syncthreads();                      // vB (ccs) dead -> gpart
            vB[part * 64 + m]       = g0;
            vB[256 + part * 64 + m] = g1;
        }
        __syncthreads();
        if (tid < 128) {
            int ns = tid >> 6, mm = tid & 63;
            const float* gp = vB + ns * 256;
            gsA[ns * 64 + mm] += gp[mm] + gp[64 + mm] + gp[128 + mm] + gp[192 + mm];
        }
        __syncthreads();

        // ---- Stages 5+6 per sample: M-tile GEMM, H2, then H1, reduce to Hs ----
        const int tk5 = tid >> 4;    // 0..15 : k rows tk5*8..+7
        const int tm5 = tid & 15;    // 0..15 : m cols tm5*4..+3
        const int kg  = tid >> 7;    // 0..1
        const int s2  = tid & 127;
        const int si  = s2 >> 4;     // H row block: 32 + si*4
        const int sj  = s2 & 15;     // H col block: sj*4

        #pragma unroll 1
        for (int ns = 0; ns < 2; ns++) {
            const float* aasN = vC + ns * 256;
            const float* eesN = vE + ns * 256;
            const float* ddsN = vD + ns * 256;
            float* HsN = Hs + ns * 2176;

            float acc2[4][4];
            #pragma unroll
            for (int i = 0; i < 4; i++)
                #pragma unroll
                for (int j = 0; j < 4; j++) acc2[i][j] = 0.0f;

            const float4* W2v  = (const float4*)W2;
            const float4* W1Tv = (const float4*)W1T;
            float4* Bs4  = (float4*)Bs;
            float4* Ast4 = (float4*)Ast;

            #pragma unroll 1
            for (int ktile = 0; ktile < 2; ktile++) {
                float acc[8][4];
                #pragma unroll
                for (int i = 0; i < 8; i++)
                    #pragma unroll
                    for (int j = 0; j < 4; j++) acc[i][j] = 0.0f;

                for (int jt = 0; jt < 256; jt += 8) {
                    {
                        int j = tid >> 5, kq = tid & 31;
                        Bs4[tid] = W2v[(jt + j) * 64 + ktile * 32 + kq];
                    }
                    if (tid < 128) {
                        int j = tid >> 4, m4 = tid & 15;
                        float4 v = W1Tv[(jt + j) * 16 + m4];
                        float aw = aasN[jt + j];
                        v.x *= aw; v.y *= aw; v.z *= aw; v.w *= aw;
                        Ast4[tid] = v;
                    }
                    __syncthreads();
                    #pragma unroll
                    for (int jj = 0; jj < 8; jj++) {
                        float4 av = Ast4[jj * 16 + tm5];
                        float4 b0 = Bs4[jj * 32 + tk5 * 2];
                        float4 b1 = Bs4[jj * 32 + tk5 * 2 + 1];
                        float am[4] = {av.x, av.y, av.z, av.w};
                        float bk[8] = {b0.x, b0.y, b0.z, b0.w, b1.x, b1.y, b1.z, b1.w};
                        #pragma unroll
                        for (int kk = 0; kk < 8; kk++)
                            #pragma unroll
                            for (int mm = 0; mm < 4; mm++)
                                acc[kk][mm] = fmaf(bk[kk], am[mm], acc[kk][mm]);
                    }
                    __syncthreads();
                }
                #pragma unroll
                for (int kk = 0; kk < 8; kk++) {
                    float4* dst = (float4*)(Mt + (tk5 * 8 + kk) * 68 + tm5 * 4);
                    *dst = make_float4(acc[kk][0], acc[kk][1], acc[kk][2], acc[kk][3]);
                }
                __syncthreads();

                // H2: acc2 += e_k * Mt[k][32+i] * Mt[k][j]
                #pragma unroll 2
                for (int k = kg; k < 128; k += 2) {
                    float w = eesN[ktile * 128 + k];
                    const float* Mr = Mt + k * 68;
                    float4 iv = *(const float4*)(Mr + 32 + si * 4);
                    float4 jv = *(const float4*)(Mr + sj * 4);
                    float ivw[4] = {iv.x * w, iv.y * w, iv.z * w, iv.w * w};
                    float jvv[4] = {jv.x, jv.y, jv.z, jv.w};
                    #pragma unroll
                    for (int ii = 0; ii < 4; ii++)
                        #pragma unroll
                        for (int jj = 0; jj < 4; jj++)
                            acc2[ii][jj] = fmaf(ivw[ii], jvv[jj], acc2[ii][jj]);
                }
                __syncthreads();
            }

            // H1: acc2 += d_k * W1T[k][32+i] * W1T[k][j], 8-row tiles
            for (int kt = 0; kt < 256; kt += 8) {
                if (tid < 128) Ast4[tid] = W1Tv[kt * 16 + tid];
                __syncthreads();
                #pragma unroll
                for (int kq = 0; kq < 4; kq++) {
                    int kk = kg * 4 + kq;
                    float w = ddsN[kt + kk];
                    float4 iv = Ast4[kk * 16 + 8 + si];
                    float4 jv = Ast4[kk * 16 + sj];
                    float ivw[4] = {iv.x * w, iv.y * w, iv.z * w, iv.w * w};
                    float jvv[4] = {jv.x, jv.y, jv.z, jv.w};
                    #pragma unroll
                    for (int ii = 0; ii < 4; ii++)
                        #pragma unroll
                        for (int jj = 0; jj < 4; jj++)
                            acc2[ii][jj] = fmaf(ivw[ii], jvv[jj], acc2[ii][jj]);
                }
                __syncthreads();
            }

            // reduce 2 k-groups into HsN (Mt free -> staging buffer)
            {
                float4* red4 = (float4*)Mt;
                if (kg == 1) {
                    float4* dst = red4 + s2 * 4;
                    #pragma unroll
                    for (int ii = 0; ii < 4; ii++)
                        dst[ii] = make_float4(acc2[ii][0], acc2[ii][1], acc2[ii][2], acc2[ii][3]);
                }
                __syncthreads();
                if (kg == 0) {
                    const float4* src = red4 + s2 * 4;
                    #pragma unroll
                    for (int ii = 0; ii < 4; ii++) {
                        float4 v = src[ii];
                        float* hrow = HsN + (si * 4 + ii) * 68 + sj * 4;
                        float4 h = *(float4*)hrow;
                        *(float4*)hrow = make_float4(h.x + acc2[ii][0] + v.x,
                                                     h.y + acc2[ii][1] + v.y,
                                                     h.z + acc2[ii][2] + v.z,
                                                     h.w + acc2[ii][3] + v.w);
                    }
                }
                __syncthreads();
            }
        }
    }

    // ---- Solve (2 warps, one per sample): (H[:,32:]+2I) qdd = g - H[:,:32] qdot ----
    float* Sv = Mt;   // 2 x 32 x 34, Mt dead
    if (tid < 64) {
        int ws = tid >> 5, lane = tid & 31;
        const float* HsN = Hs + ws * 2176;
        float* SvN = Sv + ws * 1088;
        const float* qd = xs + ws * 64 + 32;
        float r = gsA[ws * 64 + lane];
        #pragma unroll 8
        for (int j = 0; j < 32; j++) r -= HsN[lane * 68 + j] * qd[j];
        #pragma unroll 8
        for (int j = 0; j < 32; j++)
            SvN[lane * 34 + j] = HsN[lane * 68 + 32 + j] + ((lane == j) ? 2.0f : 0.0f);
        SvN[lane * 34 + 32] = r;
        __syncwarp();

        for (int p = 0; p < 32; p++) {
            float v = (lane >= p) ? fabsf(SvN[lane * 34 + p]) : -1.0f;
            int idx = lane;
            #pragma unroll
            for (int off = 16; off; off >>= 1) {
                float v2 = __shfl_xor_sync(0xffffffffu, v, off);
                int   i2 = __shfl_xor_sync(0xffffffffu, idx, off);
                if (v2 > v || (v2 == v && i2 < idx)) { v = v2; idx = i2; }
            }
            if (idx != p) {
                float t1 = SvN[p * 34 + lane];
                SvN[p * 34 + lane]   = SvN[idx * 34 + lane];
                SvN[idx * 34 + lane] = t1;
                if (lane == 0) {
                    float t2 = SvN[p * 34 + 32];
                    SvN[p * 34 + 32]   = SvN[idx * 34 + 32];
                    SvN[idx * 34 + 32] = t2;
                }
            }
            __syncwarp();
            float pinvv = 1.0f / SvN[p * 34 + p];
            if (lane != p) {
                float f = SvN[lane * 34 + p] * pinvv;
                for (int c = p; c < 33; c++)
                    SvN[lane * 34 + c] -= f * SvN[p * 34 + c];
            }
            __syncwarp();
        }
        float qdd = SvN[lane * 34 + 32] / SvN[lane * 34 + lane];
        int sample = b * 2 + ws;
        out[sample * 64 + lane]      = xs[ws * 64 + 32 + lane];
        out[sample * 64 + 32 + lane] = qdd;
    }
}

extern "C" void kernel_launch(void* const* d_in, const int* in_sizes, int n_in,
                              void* d_out, int out_size)
{
    const float* x   = (const float*)d_in[0];
    const float* W1m = (const float*)d_in[1];
    const float* b1m = (const float*)d_in[2];
    const float* W2m = (const float*)d_in[3];
    const float* b2m = (const float*)d_in[4];
    const float* W3m = (const float*)d_in[5];
    const float* W1q = (const float*)d_in[6];
    const float* b1q = (const float*)d_in[7];
    const float* W2q = (const float*)d_in[8];
    const float* b2q = (const float*)d_in[9];
    const float* W3q = (const float*)d_in[10];
    float* out = (float*)d_out;

    int B = in_sizes[0] / 64;

    prep_kernel<<<256, 256>>>(W1m, W2m, W1q, W2q);
    cudaFuncSetAttribute(lnn_kernel, cudaFuncAttributeMaxDynamicSharedMemorySize, SMEM_BYTES);
    lnn_kernel<<<B / 2, 256, SMEM_BYTES>>>(x, W1m, b1m, W2m, b2m, W3m,
                                           W1q, b1q, W2q, b2q, W3q, out);
}

// round 8
// speedup vs baseline: 1.4703x; 1.4703x over previous
#include <cuda_runtime.h>
#include <math.h>
#include <stdint.h>

#define HD 256
#define DD 64

__device__ float g_W1T[2 * DD * HD];   // [pass][(j*64 + m)]
__device__ float g_W2T[2 * HD * HD];   // [pass][(k*256 + j)]

__global__ void prep_kernel(const float* __restrict__ W1m, const float* __restrict__ W2m,
                            const float* __restrict__ W1q, const float* __restrict__ W2q)
{
    int t = blockIdx.x * blockDim.x + threadIdx.x;
    if (t < DD * HD) {
        int j = t >> 6, m = t & 63;
        g_W1T[t]           = W1m[m * HD + j];
        g_W1T[DD * HD + t] = W1q[m * HD + j];
    }
    if (t < HD * HD) {
        int k = t >> 8, j = t & 255;
        g_W2T[t]           = W2m[j * HD + k];
        g_W2T[HD * HD + t] = W2q[j * HD + k];
    }
}

__device__ __forceinline__ uint32_t to_tf32(float x) {
    uint32_t r;
    asm("cvt.rna.tf32.f32 %0, %1;" : "=r"(r) : "f"(x));
    return r;
}

// Shared memory (floats), 1 sample per CTA:
//   MsT  [256][68]  17408  (M, k-major; reused as reduction staging + Sv)
//   W2s  [16][264]   4224  (tf32 W2 j-tile for mma B fragments)
//   Asj  [16][72]    1152  (tf32 scaled W1T j-tile for mma A fragments; H1 staging)
//   Hs   [32][68]    2176
//   h1s..aus 7*256 = 1792
//   xs 64, gsA 64, gpart 256
#define SMEM_FLOATS (17408 + 4224 + 1152 + 2176 + 1792 + 64 + 64 + 256)
#define SMEM_BYTES  (SMEM_FLOATS * 4)

__global__ __launch_bounds__(256, 2)
void lnn_kernel(const float* __restrict__ x,
                const float* __restrict__ W1m, const float* __restrict__ b1m,
                const float* __restrict__ W2m, const float* __restrict__ b2m,
                const float* __restrict__ W3m,
                const float* __restrict__ W1q, const float* __restrict__ b1q,
                const float* __restrict__ W2q, const float* __restrict__ b2q,
                const float* __restrict__ W3q,
                float* __restrict__ out)
{
    extern __shared__ float sm[];
    float* MsT   = sm;                 // 17408 (pitch 68)
    float* W2s   = MsT + 17408;        // 4224  (pitch 264)
    float* Asj   = W2s + 4224;         // 1152  (pitch 72)
    float* Hs    = Asj + 1152;         // 2176
    float* h1s   = Hs + 2176;          // 256
    float* aas   = h1s + 256;
    float* sss   = aas + 256;
    float* ccs   = sss + 256;
    float* ees   = ccs + 256;
    float* dds   = ees + 256;
    float* aus   = dds + 256;
    float* xs    = aus + 256;          // 64
    float* gsA   = xs + 64;            // 64
    float* gpart = gsA + 64;           // 256

    const int tid = threadIdx.x;
    const int b   = blockIdx.x;

    for (int q = tid; q < 2176; q += 256) Hs[q] = 0.0f;
    if (tid < 64) { gsA[tid] = 0.0f; xs[tid] = x[b * 64 + tid]; }
    __syncthreads();

    #pragma unroll 1
    for (int pass = 0; pass < 2; pass++) {
        const float* W1  = pass ? W1q : W1m;
        const float* b1  = pass ? b1q : b1m;
        const float* W2  = pass ? W2q : W2m;
        const float* b2  = pass ? b2q : b2m;
        const float* W3  = pass ? W3q : W3m;
        const float* W1T = g_W1T + pass * (DD * HD);
        const float* W2T = g_W2T + pass * (HD * HD);

        // ---- Stage 1: z1 = x W1 + b1 ; h1, a = act', s = act'' ----
        {
            int j = tid;
            float zx = b1[j], zy = 0.f, zz2 = 0.f, zw = 0.f;
            const float4* xv = (const float4*)xs;
            #pragma unroll 4
            for (int i4 = 0; i4 < 16; i4++) {
                float4 v = xv[i4];
                int i = i4 * 4;
                zx  = fmaf(v.x, W1[(i + 0) * HD + j], zx);
                zy  = fmaf(v.y, W1[(i + 1) * HD + j], zy);
                zz2 = fmaf(v.z, W1[(i + 2) * HD + j], zz2);
                zw  = fmaf(v.w, W1[(i + 3) * HD + j], zw);
            }
            float z = (zx + zy) + (zz2 + zw);
            float h, a, s;
            if (pass == 0) {
                float sg = 1.0f / (1.0f + __expf(-z));
                h = fmaxf(z, 0.0f) + log1pf(__expf(-fabsf(z)));
                a = sg;
                s = sg * (1.0f - sg);
            } else {
                float t = tanhf(0.5f * z);
                float o = 1.0f - t * t;
                h = z * t;
                a = fmaf(0.5f * z, o, t);
                s = o * (1.0f - 0.5f * z * t);
            }
            h1s[j] = h; aas[j] = a; sss[j] = s;
        }
        __syncthreads();

        // ---- Stage 2: z2 = h1 W2 + b2 ; c = act'(z2)*w3, e = act''(z2)*w3 ----
        {
            int k = tid;
            float zx = b2[k], zy = 0.f, zz2 = 0.f, zw = 0.f;
            const float4* hv4 = (const float4*)h1s;
            #pragma unroll 4
            for (int l4 = 0; l4 < 64; l4++) {
                float4 v = hv4[l4];
                int l = l4 * 4;
                zx  = fmaf(v.x, W2[(l + 0) * HD + k], zx);
                zy  = fmaf(v.y, W2[(l + 1) * HD + k], zy);
                zz2 = fmaf(v.z, W2[(l + 2) * HD + k], zz2);
                zw  = fmaf(v.w, W2[(l + 3) * HD + k], zw);
            }
            float z = (zx + zy) + (zz2 + zw);
            float a, s;
            if (pass == 0) {
                float sg = 1.0f / (1.0f + __expf(-z));
                a = sg;
                s = sg * (1.0f - sg);
            } else {
                float t = tanhf(0.5f * z);
                float o = 1.0f - t * t;
                a = fmaf(0.5f * z, o, t);
                s = o * (1.0f - 0.5f * z * t);
            }
            float w3v = W3[k];
            ccs[k] = a * w3v;
            ees[k] = s * w3v;
        }
        __syncthreads();

        // ---- Stage 3: u = W2 c ; d = s*u, au = a*u ----
        {
            int j = tid;
            float ux = 0.f, uy = 0.f, uz = 0.f, uw = 0.f;
            const float4* cv4 = (const float4*)ccs;
            #pragma unroll 4
            for (int k4 = 0; k4 < 64; k4++) {
                float4 v = cv4[k4];
                int k = k4 * 4;
                ux = fmaf(v.x, W2T[(k + 0) * HD + j], ux);
                uy = fmaf(v.y, W2T[(k + 1) * HD + j], uy);
                uz = fmaf(v.z, W2T[(k + 2) * HD + j], uz);
                uw = fmaf(v.w, W2T[(k + 3) * HD + j], uw);
            }
            float u = (ux + uy) + (uz + uw);
            dds[j] = sss[j] * u;
            aus[j] = aas[j] * u;
        }
        __syncthreads();

        // ---- Stage 4: gradient g = W1 (a*u), 4-way j-split ----
        {
            int m = tid & 63, part = tid >> 6;
            const float* W1Tp = W1T + part * 64 * 64;
            const float4* av4 = (const float4*)(aus + part * 64);
            float gx = 0.f, gy = 0.f, gz = 0.f, gw = 0.f;
            #pragma unroll 4
            for (int j4 = 0; j4 < 16; j4++) {
                float4 v = av4[j4];
                int jj = j4 * 4;
                gx = fmaf(W1Tp[(jj + 0) * 64 + m], v.x, gx);
                gy = fmaf(W1Tp[(jj + 1) * 64 + m], v.y, gy);
                gz = fmaf(W1Tp[(jj + 2) * 64 + m], v.z, gz);
                gw = fmaf(W1Tp[(jj + 3) * 64 + m], v.w, gw);
            }
            gpart[part * 64 + m] = (gx + gy) + (gz + gw);
        }
        __syncthreads();
        if (tid < 64)
            gsA[tid] += gpart[tid] + gpart[64 + tid] + gpart[128 + tid] + gpart[192 + tid];

        // ---- Stage 5 (TENSOR): M[m][k2] = sum_j (a_j W1T[j][m]) W2[j][k2] ----
        // tf32 mma.m16n8k8: 8 warps = 4 m-tiles x 2 n-halves; acc 16 n-tiles each.
        {
            const int wid = tid >> 5, lane = tid & 31;
            const int mb = (wid & 3) * 16;
            const int nbase = (wid >> 2) * 128;
            const int g = lane >> 2, t4 = lane & 3;

            float acc[16][4];
            #pragma unroll
            for (int i = 0; i < 16; i++)
                #pragma unroll
                for (int j = 0; j < 4; j++) acc[i][j] = 0.f;

            const float4* W2v = (const float4*)W2;

            #pragma unroll 1
            for (int jt = 0; jt < 256; jt += 16) {
                // stage A tile: Asj[jl][m] = tf32(W1T[jt+jl][m] * a_{jt+jl}), pitch 72
                #pragma unroll
                for (int r = 0; r < 4; r++) {
                    int f = tid + r * 256;
                    int jl = f >> 6, m = f & 63;
                    float av = W1T[(jt + jl) * 64 + m] * aas[jt + jl];
                    Asj[jl * 72 + m] = __uint_as_float(to_tf32(av));
                }
                // stage B tile: W2s[jl][n] = tf32(W2[jt+jl][n]), pitch 264
                #pragma unroll
                for (int r = 0; r < 4; r++) {
                    int f = tid + r * 256;
                    int jl = f >> 6, n4 = f & 63;
                    float4 v = W2v[(jt + jl) * 64 + n4];
                    float4 o;
                    o.x = __uint_as_float(to_tf32(v.x));
                    o.y = __uint_as_float(to_tf32(v.y));
                    o.z = __uint_as_float(to_tf32(v.z));
                    o.w = __uint_as_float(to_tf32(v.w));
                    *(float4*)(W2s + jl * 264 + n4 * 4) = o;
                }
                __syncthreads();

                #pragma unroll
                for (int s = 0; s < 2; s++) {
                    int jb = s * 8;
                    uint32_t a0 = __float_as_uint(Asj[(jb + t4) * 72 + mb + g]);
                    uint32_t a1 = __float_as_uint(Asj[(jb + t4) * 72 + mb + g + 8]);
                    uint32_t a2 = __float_as_uint(Asj[(jb + t4 + 4) * 72 + mb + g]);
                    uint32_t a3 = __float_as_uint(Asj[(jb + t4 + 4) * 72 + mb + g + 8]);
                    #pragma unroll
                    for (int nt = 0; nt < 16; nt++) {
                        int nb = nbase + nt * 8;
                        uint32_t b0 = __float_as_uint(W2s[(jb + t4) * 264 + nb + g]);
                        uint32_t b1 = __float_as_uint(W2s[(jb + t4 + 4) * 264 + nb + g]);
                        asm volatile(
                            "mma.sync.aligned.m16n8k8.row.col.f32.tf32.tf32.f32 "
                            "{%0,%1,%2,%3}, {%4,%5,%6,%7}, {%8,%9}, {%0,%1,%2,%3};\n"
                            : "+f"(acc[nt][0]), "+f"(acc[nt][1]),
                              "+f"(acc[nt][2]), "+f"(acc[nt][3])
                            : "r"(a0), "r"(a1), "r"(a2), "r"(a3), "r"(b0), "r"(b1));
                    }
                }
                __syncthreads();
            }

            // epilogue: MsT[n][m] (k-major), conflict-free STS.32
            #pragma unroll
            for (int nt = 0; nt < 16; nt++) {
                int n0 = nbase + nt * 8 + t4 * 2;
                int m0 = mb + g;
                MsT[n0 * 68 + m0]           = acc[nt][0];
                MsT[(n0 + 1) * 68 + m0]     = acc[nt][1];
                MsT[n0 * 68 + m0 + 8]       = acc[nt][2];
                MsT[(n0 + 1) * 68 + m0 + 8] = acc[nt][3];
            }
        }
        __syncthreads();

        // ---- Stage 6: H rows 32..63 += W1 diag(d) W1^T + M diag(e) M^T ----
        {
            const int kg = tid >> 7;     // 0..1 (k-split)
            const int s2 = tid & 127;
            const int si = s2 >> 4;      // i block: rows 32 + si*4
            const int sj = s2 & 15;      // j block: cols sj*4
            float acc2[4][4];
            #pragma unroll
            for (int i = 0; i < 4; i++)
                #pragma unroll
                for (int j = 0; j < 4; j++) acc2[i][j] = 0.0f;

            // H2: acc2 += e_k * M[k][32+i] * M[k][j]
            #pragma unroll 2
            for (int k = kg; k < 256; k += 2) {
                float w = ees[k];
                const float* Mr = MsT + k * 68;
                float4 iv = *(const float4*)(Mr + 32 + si * 4);
                float4 jv = *(const float4*)(Mr + sj * 4);
                float ivw[4] = {iv.x * w, iv.y * w, iv.z * w, iv.w * w};
                float jvv[4] = {jv.x, jv.y, jv.z, jv.w};
                #pragma unroll
                for (int ii = 0; ii < 4; ii++)
                    #pragma unroll
                    for (int jj = 0; jj < 4; jj++)
                        acc2[ii][jj] = fmaf(ivw[ii], jvv[jj], acc2[ii][jj]);
            }

            // H1: acc2 += d_k * W1T[k][32+i] * W1T[k][j], 8-row tiles in Asj
            const float4* W1Tv = (const float4*)W1T;
            float4* Ast4 = (float4*)Asj;
            for (int kt = 0; kt < 256; kt += 8) {
                __syncthreads();
                if (tid < 128) Ast4[tid] = W1Tv[kt * 16 + tid];
                __syncthreads();
                #pragma unroll
                for (int kq = 0; kq < 4; kq++) {
                    int kk = kg * 4 + kq;
                    float w = dds[kt + kk];
                    float4 iv = Ast4[kk * 16 + 8 + si];
                    float4 jv = Ast4[kk * 16 + sj];
                    float ivw[4] = {iv.x * w, iv.y * w, iv.z * w, iv.w * w};
                    float jvv[4] = {jv.x, jv.y, jv.z, jv.w};
                    #pragma unroll
                    for (int ii = 0; ii < 4; ii++)
                        #pragma unroll
                        for (int jj = 0; jj < 4; jj++)
                            acc2[ii][jj] = fmaf(ivw[ii], jvv[jj], acc2[ii][jj]);
                }
            }
            __syncthreads();

            // reduce 2 k-groups into Hs (MsT free -> staging buffer)
            {
                float4* red4 = (float4*)MsT;
                if (kg == 1) {
                    float4* dst = red4 + s2 * 4;
                    #pragma unroll
                    for (int ii = 0; ii < 4; ii++)
                        dst[ii] = make_float4(acc2[ii][0], acc2[ii][1], acc2[ii][2], acc2[ii][3]);
                }
                __syncthreads();
                if (kg == 0) {
                    const float4* src = red4 + s2 * 4;
                    #pragma unroll
                    for (int ii = 0; ii < 4; ii++) {
                        float4 v = src[ii];
                        float* hrow = Hs + (si * 4 + ii) * 68 + sj * 4;
                        float4 h = *(float4*)hrow;
                        *(float4*)hrow = make_float4(h.x + acc2[ii][0] + v.x,
                                                     h.y + acc2[ii][1] + v.y,
                                                     h.z + acc2[ii][2] + v.z,
                                                     h.w + acc2[ii][3] + v.w);
                    }
                }
            }
        }
        __syncthreads();
    }

    // ---- Solve: (Hs[:,32:64] + 2I) qdd = g[:32] - Hs[:,0:32] qdot ----
    float* Sv = MsT;   // dead, reuse
    if (tid < 32) {
        int i = tid;
        float r = gsA[i];
        #pragma unroll 8
        for (int j = 0; j < 32; j++) r -= Hs[i * 68 + j] * xs[32 + j];
        #pragma unroll 8
        for (int j = 0; j < 32; j++)
            Sv[i * 34 + j] = Hs[i * 68 + 32 + j] + ((i == j) ? 2.0f : 0.0f);
        Sv[i * 34 + 32] = r;
    }
    __syncthreads();
    if (tid < 32) {
        int lane = tid;
        for (int p = 0; p < 32; p++) {
            float v = (lane >= p) ? fabsf(Sv[lane * 34 + p]) : -1.0f;
            int idx = lane;
            #pragma unroll
            for (int off = 16; off; off >>= 1) {
                float v2 = __shfl_xor_sync(0xffffffffu, v, off);
                int   i2 = __shfl_xor_sync(0xffffffffu, idx, off);
                if (v2 > v || (v2 == v && i2 < idx)) { v = v2; idx = i2; }
            }
            if (idx != p) {
                float t1 = Sv[p * 34 + lane];
                Sv[p * 34 + lane]   = Sv[idx * 34 + lane];
                Sv[idx * 34 + lane] = t1;
                if (lane == 0) {
                    float t2 = Sv[p * 34 + 32];
                    Sv[p * 34 + 32]   = Sv[idx * 34 + 32];
                    Sv[idx * 34 + 32] = t2;
                }
            }
            __syncwarp();
            float pinvv = 1.0f / Sv[p * 34 + p];
            if (lane != p) {
                float f = Sv[lane * 34 + p] * pinvv;
                for (int c = p; c < 33; c++)
                    Sv[lane * 34 + c] -= f * Sv[p * 34 + c];
            }
            __syncwarp();
        }
        float qdd = Sv[lane * 34 + 32] / Sv[lane * 34 + lane];
        out[b * 64 + lane]      = xs[32 + lane];
        out[b * 64 + 32 + lane] = qdd;
    }
}

extern "C" void kernel_launch(void* const* d_in, const int* in_sizes, int n_in,
                              void* d_out, int out_size)
{
    const float* x   = (const float*)d_in[0];
    const float* W1m = (const float*)d_in[1];
    const float* b1m = (const float*)d_in[2];
    const float* W2m = (const float*)d_in[3];
    const float* b2m = (const float*)d_in[4];
    const float* W3m = (const float*)d_in[5];
    const float* W1q = (const float*)d_in[6];
    const float* b1q = (const float*)d_in[7];
    const float* W2q = (const float*)d_in[8];
    const float* b2q = (const float*)d_in[9];
    const float* W3q = (const float*)d_in[10];
    float* out = (float*)d_out;

    int B = in_sizes[0] / 64;

    prep_kernel<<<256, 256>>>(W1m, W2m, W1q, W2q);
    cudaFuncSetAttribute(lnn_kernel, cudaFuncAttributeMaxDynamicSharedMemorySize, SMEM_BYTES);
    lnn_kernel<<<B, 256, SMEM_BYTES>>>(x, W1m, b1m, W2m, b2m, W3m,
                                       W1q, b1q, W2q, b2q, W3q, out);
}

// round 9
// speedup vs baseline: 1.7407x; 1.1839x over previous
#include <cuda_runtime.h>
#include <math.h>
#include <stdint.h>

#define HD 256
#define DD 64

__device__ float g_W1T[2 * DD * HD];   // [pass][(j*64 + m)]
__device__ float g_W2T[2 * HD * HD];   // [pass][(k*256 + j)]

__global__ void prep_kernel(const float* __restrict__ W1m, const float* __restrict__ W2m,
                            const float* __restrict__ W1q, const float* __restrict__ W2q)
{
    int t = blockIdx.x * blockDim.x + threadIdx.x;
    if (t < DD * HD) {
        int j = t >> 6, m = t & 63;
        g_W1T[t]           = W1m[m * HD + j];
        g_W1T[DD * HD + t] = W1q[m * HD + j];
    }
    if (t < HD * HD) {
        int k = t >> 8, j = t & 255;
        g_W2T[t]           = W2m[j * HD + k];
        g_W2T[HD * HD + t] = W2q[j * HD + k];
    }
}

__device__ __forceinline__ uint32_t to_tf32(float x) {
    uint32_t r;
    asm("cvt.rna.tf32.f32 %0, %1;" : "=r"(r) : "f"(x));
    return r;
}

#define MMA_TF32(acc, a0, a1, a2, a3, b0, b1)                                   \
    asm volatile(                                                               \
        "mma.sync.aligned.m16n8k8.row.col.f32.tf32.tf32.f32 "                   \
        "{%0,%1,%2,%3}, {%4,%5,%6,%7}, {%8,%9}, {%0,%1,%2,%3};\n"               \
        : "+f"(acc[0]), "+f"(acc[1]), "+f"(acc[2]), "+f"(acc[3])                \
        : "r"(a0), "r"(a1), "r"(a2), "r"(a3), "r"(b0), "r"(b1))

// Shared memory (floats), 1 sample per CTA:
//   MsT  [256][68]  17408  (M, k-major; reused as Sv in solve)
//   W2s  [16][264]   4224  (tf32 W2 j-tile for mma B fragments)
//   Asj  [16][72]    1152  (stage-5 A tile; H1 W1T tile)
//   Hs   [32][68]    2176
//   h1s..aus 7*256 = 1792
//   xs 64, gsA 64, gpart 256
#define SMEM_FLOATS (17408 + 4224 + 1152 + 2176 + 1792 + 64 + 64 + 256)
#define SMEM_BYTES  (SMEM_FLOATS * 4)

__global__ __launch_bounds__(256, 2)
void lnn_kernel(const float* __restrict__ x,
                const float* __restrict__ W1m, const float* __restrict__ b1m,
                const float* __restrict__ W2m, const float* __restrict__ b2m,
                const float* __restrict__ W3m,
                const float* __restrict__ W1q, const float* __restrict__ b1q,
                const float* __restrict__ W2q, const float* __restrict__ b2q,
                const float* __restrict__ W3q,
                float* __restrict__ out)
{
    extern __shared__ float sm[];
    float* MsT   = sm;                 // 17408 (pitch 68)
    float* W2s   = MsT + 17408;        // 4224  (pitch 264)
    float* Asj   = W2s + 4224;         // 1152  (pitch 72)
    float* Hs    = Asj + 1152;         // 2176
    float* h1s   = Hs + 2176;          // 256
    float* aas   = h1s + 256;
    float* sss   = aas + 256;
    float* ccs   = sss + 256;
    float* ees   = ccs + 256;
    float* dds   = ees + 256;
    float* aus   = dds + 256;
    float* xs    = aus + 256;          // 64
    float* gsA   = xs + 64;            // 64
    float* gpart = gsA + 64;           // 256

    const int tid = threadIdx.x;
    const int b   = blockIdx.x;

    for (int q = tid; q < 2176; q += 256) Hs[q] = 0.0f;
    if (tid < 64) { gsA[tid] = 0.0f; xs[tid] = x[b * 64 + tid]; }
    __syncthreads();

    #pragma unroll 1
    for (int pass = 0; pass < 2; pass++) {
        const float* W1  = pass ? W1q : W1m;
        const float* b1  = pass ? b1q : b1m;
        const float* W2  = pass ? W2q : W2m;
        const float* b2  = pass ? b2q : b2m;
        const float* W3  = pass ? W3q : W3m;
        const float* W1T = g_W1T + pass * (DD * HD);
        const float* W2T = g_W2T + pass * (HD * HD);

        // ---- Stage 1: z1 = x W1 + b1 ; h1, a = act', s = act'' ----
        {
            int j = tid;
            float zx = b1[j], zy = 0.f, zz2 = 0.f, zw = 0.f;
            const float4* xv = (const float4*)xs;
            #pragma unroll 4
            for (int i4 = 0; i4 < 16; i4++) {
                float4 v = xv[i4];
                int i = i4 * 4;
                zx  = fmaf(v.x, W1[(i + 0) * HD + j], zx);
                zy  = fmaf(v.y, W1[(i + 1) * HD + j], zy);
                zz2 = fmaf(v.z, W1[(i + 2) * HD + j], zz2);
                zw  = fmaf(v.w, W1[(i + 3) * HD + j], zw);
            }
            float z = (zx + zy) + (zz2 + zw);
            float h, a, s;
            if (pass == 0) {
                float sg = 1.0f / (1.0f + __expf(-z));
                h = fmaxf(z, 0.0f) + log1pf(__expf(-fabsf(z)));
                a = sg;
                s = sg * (1.0f - sg);
            } else {
                float t = tanhf(0.5f * z);
                float o = 1.0f - t * t;
                h = z * t;
                a = fmaf(0.5f * z, o, t);
                s = o * (1.0f - 0.5f * z * t);
            }
            h1s[j] = h; aas[j] = a; sss[j] = s;
        }
        __syncthreads();

        // ---- Stage 2: z2 = h1 W2 + b2 ; c = act'(z2)*w3, e = act''(z2)*w3 ----
        {
            int k = tid;
            float zx = b2[k], zy = 0.f, zz2 = 0.f, zw = 0.f;
            const float4* hv4 = (const float4*)h1s;
            #pragma unroll 4
            for (int l4 = 0; l4 < 64; l4++) {
                float4 v = hv4[l4];
                int l = l4 * 4;
                zx  = fmaf(v.x, W2[(l + 0) * HD + k], zx);
                zy  = fmaf(v.y, W2[(l + 1) * HD + k], zy);
                zz2 = fmaf(v.z, W2[(l + 2) * HD + k], zz2);
                zw  = fmaf(v.w, W2[(l + 3) * HD + k], zw);
            }
            float z = (zx + zy) + (zz2 + zw);
            float a, s;
            if (pass == 0) {
                float sg = 1.0f / (1.0f + __expf(-z));
                a = sg;
                s = sg * (1.0f - sg);
            } else {
                float t = tanhf(0.5f * z);
                float o = 1.0f - t * t;
                a = fmaf(0.5f * z, o, t);
                s = o * (1.0f - 0.5f * z * t);
            }
            float w3v = W3[k];
            ccs[k] = a * w3v;
            ees[k] = s * w3v;
        }
        __syncthreads();

        // ---- Stage 3: u = W2 c ; d = s*u, au = a*u ----
        {
            int j = tid;
            float ux = 0.f, uy = 0.f, uz = 0.f, uw = 0.f;
            const float4* cv4 = (const float4*)ccs;
            #pragma unroll 4
            for (int k4 = 0; k4 < 64; k4++) {
                float4 v = cv4[k4];
                int k = k4 * 4;
                ux = fmaf(v.x, W2T[(k + 0) * HD + j], ux);
                uy = fmaf(v.y, W2T[(k + 1) * HD + j], uy);
                uz = fmaf(v.z, W2T[(k + 2) * HD + j], uz);
                uw = fmaf(v.w, W2T[(k + 3) * HD + j], uw);
            }
            float u = (ux + uy) + (uz + uw);
            dds[j] = sss[j] * u;
            aus[j] = aas[j] * u;
        }
        __syncthreads();

        // ---- Stage 4: gradient g = W1 (a*u), 4-way j-split ----
        {
            int m = tid & 63, part = tid >> 6;
            const float* W1Tp = W1T + part * 64 * 64;
            const float4* av4 = (const float4*)(aus + part * 64);
            float gx = 0.f, gy = 0.f, gz = 0.f, gw = 0.f;
            #pragma unroll 4
            for (int j4 = 0; j4 < 16; j4++) {
                float4 v = av4[j4];
                int jj = j4 * 4;
                gx = fmaf(W1Tp[(jj + 0) * 64 + m], v.x, gx);
                gy = fmaf(W1Tp[(jj + 1) * 64 + m], v.y, gy);
                gz = fmaf(W1Tp[(jj + 2) * 64 + m], v.z, gz);
                gw = fmaf(W1Tp[(jj + 3) * 64 + m], v.w, gw);
            }
            gpart[part * 64 + m] = (gx + gy) + (gz + gw);
        }
        __syncthreads();
        if (tid < 64)
            gsA[tid] += gpart[tid] + gpart[64 + tid] + gpart[128 + tid] + gpart[192 + tid];

        // ---- Stage 5 (TENSOR): M[m][k2] = sum_j (a_j W1T[j][m]) W2[j][k2] ----
        {
            const int wid = tid >> 5, lane = tid & 31;
            const int mb = (wid & 3) * 16;
            const int nbase = (wid >> 2) * 128;
            const int g = lane >> 2, t4 = lane & 3;

            float acc[16][4];
            #pragma unroll
            for (int i = 0; i < 16; i++)
                #pragma unroll
                for (int j = 0; j < 4; j++) acc[i][j] = 0.f;

            const float4* W2v = (const float4*)W2;

            #pragma unroll 1
            for (int jt = 0; jt < 256; jt += 16) {
                #pragma unroll
                for (int r = 0; r < 4; r++) {
                    int f = tid + r * 256;
                    int jl = f >> 6, m = f & 63;
                    float av = W1T[(jt + jl) * 64 + m] * aas[jt + jl];
                    Asj[jl * 72 + m] = __uint_as_float(to_tf32(av));
                }
                #pragma unroll
                for (int r = 0; r < 4; r++) {
                    int f = tid + r * 256;
                    int jl = f >> 6, n4 = f & 63;
                    float4 v = W2v[(jt + jl) * 64 + n4];
                    float4 o;
                    o.x = __uint_as_float(to_tf32(v.x));
                    o.y = __uint_as_float(to_tf32(v.y));
                    o.z = __uint_as_float(to_tf32(v.z));
                    o.w = __uint_as_float(to_tf32(v.w));
                    *(float4*)(W2s + jl * 264 + n4 * 4) = o;
                }
                __syncthreads();

                #pragma unroll
                for (int s = 0; s < 2; s++) {
                    int jb = s * 8;
                    uint32_t a0 = __float_as_uint(Asj[(jb + t4) * 72 + mb + g]);
                    uint32_t a1 = __float_as_uint(Asj[(jb + t4) * 72 + mb + g + 8]);
                    uint32_t a2 = __float_as_uint(Asj[(jb + t4 + 4) * 72 + mb + g]);
                    uint32_t a3 = __float_as_uint(Asj[(jb + t4 + 4) * 72 + mb + g + 8]);
                    #pragma unroll
                    for (int nt = 0; nt < 16; nt++) {
                        int nb = nbase + nt * 8;
                        uint32_t b0 = __float_as_uint(W2s[(jb + t4) * 264 + nb + g]);
                        uint32_t b1 = __float_as_uint(W2s[(jb + t4 + 4) * 264 + nb + g]);
                        MMA_TF32(acc[nt], a0, a1, a2, a3, b0, b1);
                    }
                }
                __syncthreads();
            }

            // epilogue: MsT[n][m] (k-major), conflict-free STS.32
            #pragma unroll
            for (int nt = 0; nt < 16; nt++) {
                int n0 = nbase + nt * 8 + t4 * 2;
                int m0 = mb + g;
                MsT[n0 * 68 + m0]           = acc[nt][0];
                MsT[(n0 + 1) * 68 + m0]     = acc[nt][1];
                MsT[n0 * 68 + m0 + 8]       = acc[nt][2];
                MsT[(n0 + 1) * 68 + m0 + 8] = acc[nt][3];
            }
        }
        __syncthreads();

        // ---- Stage 6 (TENSOR): Hs[i][j] += sum_k w_k V[k][32+i] V[k][j] ----
        // k<256: V=W1T (staged in Asj), w=dds. k>=256: V=M (MsT direct), w=ees.
        // 8 warps = 2 m-tiles (i) x 4 n-groups (j, 16 each); hacc[2][4]/thread.
        {
            const int wid = tid >> 5, lane = tid & 31;
            const int g = lane >> 2, t4 = lane & 3;
            const int mH = (wid & 1) * 16;
            const int nH = (wid >> 1) * 16;
            float hacc[2][4];
            #pragma unroll
            for (int i = 0; i < 2; i++)
                #pragma unroll
                for (int j = 0; j < 4; j++) hacc[i][j] = 0.f;

            // H1: weights dds, V tiles from global W1T via Asj (pitch 72)
            #pragma unroll 1
            for (int kt = 0; kt < 256; kt += 16) {
                #pragma unroll
                for (int r = 0; r < 4; r++) {
                    int f = tid + r * 256;
                    int kl = f >> 6, m = f & 63;
                    Asj[kl * 72 + m] = W1T[(kt + kl) * 64 + m];
                }
                __syncthreads();
                #pragma unroll
                for (int s = 0; s < 2; s++) {
                    int kb = s * 8;
                    float w0 = dds[kt + kb + t4];
                    float w1 = dds[kt + kb + t4 + 4];
                    const float* r0 = Asj + (kb + t4) * 72;
                    const float* r1 = Asj + (kb + t4 + 4) * 72;
                    uint32_t a0 = to_tf32(r0[32 + mH + g] * w0);
                    uint32_t a1 = to_tf32(r0[32 + mH + g + 8] * w0);
                    uint32_t a2 = to_tf32(r1[32 + mH + g] * w1);
                    uint32_t a3 = to_tf32(r1[32 + mH + g + 8] * w1);
                    #pragma unroll
                    for (int nt = 0; nt < 2; nt++) {
                        int nb = nH + nt * 8;
                        uint32_t b0 = to_tf32(r0[nb + g]);
                        uint32_t b1 = to_tf32(r1[nb + g]);
                        MMA_TF32(hacc[nt], a0, a1, a2, a3, b0, b1);
                    }
                }
                __syncthreads();
            }

            // H2: weights ees, V rows direct from MsT (pitch 68) — no syncs
            #pragma unroll 2
            for (int kt = 0; kt < 256; kt += 8) {
                float w0 = ees[kt + t4];
                float w1 = ees[kt + t4 + 4];
                const float* r0 = MsT + (kt + t4) * 68;
                const float* r1 = MsT + (kt + t4 + 4) * 68;
                uint32_t a0 = to_tf32(r0[32 + mH + g] * w0);
                uint32_t a1 = to_tf32(r0[32 + mH + g + 8] * w0);
                uint32_t a2 = to_tf32(r1[32 + mH + g] * w1);
                uint32_t a3 = to_tf32(r1[32 + mH + g + 8] * w1);
                #pragma unroll
                for (int nt = 0; nt < 2; nt++) {
                    int nb = nH + nt * 8;
                    uint32_t b0 = to_tf32(r0[nb + g]);
                    uint32_t b1 = to_tf32(r1[nb + g]);
                    MMA_TF32(hacc[nt], a0, a1, a2, a3, b0, b1);
                }
            }

            // epilogue: Hs += (each (i,j) owned by exactly one thread)
            #pragma unroll
            for (int nt = 0; nt < 2; nt++) {
                int j0 = nH + nt * 8 + t4 * 2;
                Hs[(mH + g) * 68 + j0]         += hacc[nt][0];
                Hs[(mH + g) * 68 + j0 + 1]     += hacc[nt][1];
                Hs[(mH + g + 8) * 68 + j0]     += hacc[nt][2];
                Hs[(mH + g + 8) * 68 + j0 + 1] += hacc[nt][3];
            }
        }
        __syncthreads();
    }

    // ---- Solve: (Hs[:,32:64] + 2I) qdd = g[:32] - Hs[:,0:32] qdot ----
    float* Sv = MsT;   // dead, reuse
    if (tid < 32) {
        int i = tid;
        float r = gsA[i];
        #pragma unroll 8
        for (int j = 0; j < 32; j++) r -= Hs[i * 68 + j] * xs[32 + j];
        #pragma unroll 8
        for (int j = 0; j < 32; j++)
            Sv[i * 34 + j] = Hs[i * 68 + 32 + j] + ((i == j) ? 2.0f : 0.0f);
        Sv[i * 34 + 32] = r;
    }
    __syncthreads();
    if (tid < 32) {
        int lane = tid;
        for (int p = 0; p < 32; p++) {
            float v = (lane >= p) ? fabsf(Sv[lane * 34 + p]) : -1.0f;
            int idx = lane;
            #pragma unroll
            for (int off = 16; off; off >>= 1) {
                float v2 = __shfl_xor_sync(0xffffffffu, v, off);
                int   i2 = __shfl_xor_sync(0xffffffffu, idx, off);
                if (v2 > v || (v2 == v && i2 < idx)) { v = v2; idx = i2; }
            }
            if (idx != p) {
                float t1 = Sv[p * 34 + lane];
                Sv[p * 34 + lane]   = Sv[idx * 34 + lane];
                Sv[idx * 34 + lane] = t1;
                if (lane == 0) {
                    float t2 = Sv[p * 34 + 32];
                    Sv[p * 34 + 32]   = Sv[idx * 34 + 32];
                    Sv[idx * 34 + 32] = t2;
                }
            }
            __syncwarp();
            float pinvv = 1.0f / Sv[p * 34 + p];
            if (lane != p) {
                float f = Sv[lane * 34 + p] * pinvv;
                for (int c = p; c < 33; c++)
                    Sv[lane * 34 + c] -= f * Sv[p * 34 + c];
            }
            __syncwarp();
        }
        float qdd = Sv[lane * 34 + 32] / Sv[lane * 34 + lane];
        out[b * 64 + lane]      = xs[32 + lane];
        out[b * 64 + 32 + lane] = qdd;
    }
}

extern "C" void kernel_launch(void* const* d_in, const int* in_sizes, int n_in,
                              void* d_out, int out_size)
{
    const float* x   = (const float*)d_in[0];
    const float* W1m = (const float*)d_in[1];
    const float* b1m = (const float*)d_in[2];
    const float* W2m = (const float*)d_in[3];
    const float* b2m = (const float*)d_in[4];
    const float* W3m = (const float*)d_in[5];
    const float* W1q = (const float*)d_in[6];
    const float* b1q = (const float*)d_in[7];
    const float* W2q = (const float*)d_in[8];
    const float* b2q = (const float*)d_in[9];
    const float* W3q = (const float*)d_in[10];
    float* out = (float*)d_out;

    int B = in_sizes[0] / 64;

    prep_kernel<<<256, 256>>>(W1m, W2m, W1q, W2q);
    cudaFuncSetAttribute(lnn_kernel, cudaFuncAttributeMaxDynamicSharedMemorySize, SMEM_BYTES);
    lnn_kernel<<<B, 256, SMEM_BYTES>>>(x, W1m, b1m, W2m, b2m, W3m,
                                       W1q, b1q, W2q, b2q, W3q, out);
}

// round 11
// speedup vs baseline: 2.3773x; 1.3657x over previous
#include <cuda_runtime.h>
#include <math.h>
#include <stdint.h>

#define HD 256
#define DD 64

__device__ float g_W1T[2 * DD * HD];   // [pass][(j*64 + m)]
__device__ float g_W2T[2 * HD * HD];   // [pass][(k*256 + j)]

__global__ void prep_kernel(const float* __restrict__ W1m, const float* __restrict__ W2m,
                            const float* __restrict__ W1q, const float* __restrict__ W2q)
{
    int t = blockIdx.x * blockDim.x + threadIdx.x;
    if (t < DD * HD) {
        int j = t >> 6, m = t & 63;
        g_W1T[t]           = W1m[m * HD + j];
        g_W1T[DD * HD + t] = W1q[m * HD + j];
    }
    if (t < HD * HD) {
        int k = t >> 8, j = t & 255;
        g_W2T[t]           = W2m[j * HD + k];
        g_W2T[HD * HD + t] = W2q[j * HD + k];
    }
}

__device__ __forceinline__ uint32_t to_tf32(float x) {
    uint32_t r;
    asm("cvt.rna.tf32.f32 %0, %1;" : "=r"(r) : "f"(x));
    return r;
}

#define MMA_TF32(acc, a0, a1, a2, a3, b0, b1)                                   \
    asm volatile(                                                               \
        "mma.sync.aligned.m16n8k8.row.col.f32.tf32.tf32.f32 "                   \
        "{%0,%1,%2,%3}, {%4,%5,%6,%7}, {%8,%9}, {%0,%1,%2,%3};\n"               \
        : "+f"(acc[0]), "+f"(acc[1]), "+f"(acc[2]), "+f"(acc[3])                \
        : "r"(a0), "r"(a1), "r"(a2), "r"(a3), "r"(b0), "r"(b1))

// Shared memory (floats), NS=2 samples per CTA:
//   Mt2  [2][128][68] 17408  M n-chunk for both samples (k-major); Sv in solve
//   W2s  [16][136]     2176  tf32 W2 (j x n-chunk) tile
//   Asj2 [16][136]     2176  tf32 scaled A tile (m' = 2x64); H1 W1T tile
//   Hs2  [2][32][65]   4160  H rows 32..63 per sample; col 64 = gsA (rows 0..31 only!)
//   vA/vB/vC/vD/vE 512 each: h1->aus | ccs->gpart | aas | sss->dds | ees
//   xs 128
#define SMEM_FLOATS (17408 + 2176 + 2176 + 4160 + 5*512 + 128)
#define SMEM_BYTES  (SMEM_FLOATS * 4)

__global__ __launch_bounds__(256, 2)
void lnn_kernel(const float* __restrict__ x,
                const float* __restrict__ W1m, const float* __restrict__ b1m,
                const float* __restrict__ W2m, const float* __restrict__ b2m,
                const float* __restrict__ W3m,
                const float* __restrict__ W1q, const float* __restrict__ b1q,
                const float* __restrict__ W2q, const float* __restrict__ b2q,
                const float* __restrict__ W3q,
                float* __restrict__ out)
{
    extern __shared__ float sm[];
    float* Mt2  = sm;                // 17408
    float* W2s  = Mt2 + 17408;       // 2176 (pitch 136)
    float* Asj2 = W2s + 2176;        // 2176 (pitch 136)
    float* Hs2  = Asj2 + 2176;       // 4160 (pitch 65; col 64 = gsA)
    float* vA   = Hs2 + 4160;        // 512
    float* vB   = vA + 512;          // 512
    float* vC   = vB + 512;          // 512
    float* vD   = vC + 512;          // 512
    float* vE   = vD + 512;          // 512
    float* xs   = vE + 512;          // 128

    const int tid = threadIdx.x;
    const int b   = blockIdx.x;      // samples 2b, 2b+1

    for (int q = tid; q < 4160; q += 256) Hs2[q] = 0.0f;
    if (tid < 128) xs[tid] = x[b * 128 + tid];
    __syncthreads();

    const int wid = tid >> 5, lane = tid & 31;
    const int g = lane >> 2, t4 = lane & 3;

    #pragma unroll 1
    for (int pass = 0; pass < 2; pass++) {
        const float* W1  = pass ? W1q : W1m;
        const float* b1  = pass ? b1q : b1m;
        const float* W2  = pass ? W2q : W2m;
        const float* b2  = pass ? b2q : b2m;
        const float* W3  = pass ? W3q : W3m;
        const float* W1T = g_W1T + pass * (DD * HD);
        const float* W2T = g_W2T + pass * (HD * HD);

        // ---- Stage 1: z1 = x W1 + b1 (both samples); h1, a, s ----
        {
            int j = tid;
            float bv = b1[j];
            float p0 = bv, p1 = 0.f, p2 = 0.f, p3 = 0.f;
            float q0 = bv, q1 = 0.f, q2 = 0.f, q3 = 0.f;
            const float4* x0 = (const float4*)xs;
            const float4* x1 = (const float4*)(xs + 64);
            #pragma unroll 4
            for (int i4 = 0; i4 < 16; i4++) {
                int i = i4 * 4;
                float w0 = W1[(i + 0) * HD + j];
                float w1 = W1[(i + 1) * HD + j];
                float w2 = W1[(i + 2) * HD + j];
                float w3 = W1[(i + 3) * HD + j];
                float4 u0 = x0[i4], u1 = x1[i4];
                p0 = fmaf(u0.x, w0, p0); q0 = fmaf(u1.x, w0, q0);
                p1 = fmaf(u0.y, w1, p1); q1 = fmaf(u1.y, w1, q1);
                p2 = fmaf(u0.z, w2, p2); q2 = fmaf(u1.z, w2, q2);
                p3 = fmaf(u0.w, w3, p3); q3 = fmaf(u1.w, w3, q3);
            }
            float z0v = (p0 + p1) + (p2 + p3);
            float z1v = (q0 + q1) + (q2 + q3);
            #pragma unroll
            for (int ns = 0; ns < 2; ns++) {
                float z = ns ? z1v : z0v;
                float h, a, s;
                if (pass == 0) {
                    float sg = 1.0f / (1.0f + __expf(-z));
                    h = fmaxf(z, 0.0f) + log1pf(__expf(-fabsf(z)));
                    a = sg;
                    s = sg * (1.0f - sg);
                } else {
                    float t = tanhf(0.5f * z);
                    float o = 1.0f - t * t;
                    h = z * t;
                    a = fmaf(0.5f * z, o, t);
                    s = o * (1.0f - 0.5f * z * t);
                }
                vA[ns * 256 + j] = h;
                vC[ns * 256 + j] = a;
                vD[ns * 256 + j] = s;
            }
        }
        __syncthreads();

        // ---- Stage 2: z2 = h1 W2 + b2 ; c, e ----
        {
            int k = tid;
            float bv = b2[k];
            float p0 = bv, p1 = 0.f, p2 = 0.f, p3 = 0.f;
            float q0 = bv, q1 = 0.f, q2 = 0.f, q3 = 0.f;
            const float4* h0 = (const float4*)vA;
            const float4* h1v = (const float4*)(vA + 256);
            #pragma unroll 4
            for (int l4 = 0; l4 < 64; l4++) {
                int l = l4 * 4;
                float w0 = W2[(l + 0) * HD + k];
                float w1 = W2[(l + 1) * HD + k];
                float w2 = W2[(l + 2) * HD + k];
                float w3 = W2[(l + 3) * HD + k];
                float4 u0 = h0[l4], u1 = h1v[l4];
                p0 = fmaf(u0.x, w0, p0); q0 = fmaf(u1.x, w0, q0);
                p1 = fmaf(u0.y, w1, p1); q1 = fmaf(u1.y, w1, q1);
                p2 = fmaf(u0.z, w2, p2); q2 = fmaf(u1.z, w2, q2);
                p3 = fmaf(u0.w, w3, p3); q3 = fmaf(u1.w, w3, q3);
            }
            float z0v = (p0 + p1) + (p2 + p3);
            float z1v = (q0 + q1) + (q2 + q3);
            float w3v = W3[k];
            #pragma unroll
            for (int ns = 0; ns < 2; ns++) {
                float z = ns ? z1v : z0v;
                float a, s;
                if (pass == 0) {
                    float sg = 1.0f / (1.0f + __expf(-z));
                    a = sg;
                    s = sg * (1.0f - sg);
                } else {
                    float t = tanhf(0.5f * z);
                    float o = 1.0f - t * t;
                    a = fmaf(0.5f * z, o, t);
                    s = o * (1.0f - 0.5f * z * t);
                }
                vB[ns * 256 + k] = a * w3v;
                vE[ns * 256 + k] = s * w3v;
            }
        }
        __syncthreads();

        // ---- Stage 3: u = W2 c ; dds = s*u, aus = a*u ----
        {
            int j = tid;
            float p0 = 0.f, p1 = 0.f, p2 = 0.f, p3 = 0.f;
            float q0 = 0.f, q1 = 0.f, q2 = 0.f, q3 = 0.f;
            const float4* c0 = (const float4*)vB;
            const float4* c1 = (const float4*)(vB + 256);
            #pragma unroll 4
            for (int k4 = 0; k4 < 64; k4++) {
                int k = k4 * 4;
                float w0 = W2T[(k + 0) * HD + j];
                float w1 = W2T[(k + 1) * HD + j];
                float w2 = W2T[(k + 2) * HD + j];
                float w3 = W2T[(k + 3) * HD + j];
                float4 u0 = c0[k4], u1 = c1[k4];
                p0 = fmaf(u0.x, w0, p0); q0 = fmaf(u1.x, w0, q0);
                p1 = fmaf(u0.y, w1, p1); q1 = fmaf(u1.y, w1, q1);
                p2 = fmaf(u0.z, w2, p2); q2 = fmaf(u1.z, w2, q2);
                p3 = fmaf(u0.w, w3, p3); q3 = fmaf(u1.w, w3, q3);
            }
            float u0v = (p0 + p1) + (p2 + p3);
            float u1v = (q0 + q1) + (q2 + q3);
            float s0 = vD[j], s1 = vD[256 + j];
            float a0 = vC[j], a1 = vC[256 + j];
            vD[j]       = s0 * u0v;  vD[256 + j] = s1 * u1v;
            vA[j]       = a0 * u0v;  vA[256 + j] = a1 * u1v;
        }
        __syncthreads();

        // ---- Stage 4: g = W1 (a*u), 4-way j-split, both samples ----
        {
            int m = tid & 63, part = tid >> 6;
            const float* W1Tp = W1T + part * 64 * 64;
            const float4* a0 = (const float4*)(vA + part * 64);
            const float4* a1 = (const float4*)(vA + 256 + part * 64);
            float p0 = 0.f, p1 = 0.f, p2 = 0.f, p3 = 0.f;
            float q0 = 0.f, q1 = 0.f, q2 = 0.f, q3 = 0.f;
            #pragma unroll 4
            for (int j4 = 0; j4 < 16; j4++) {
                int jj = j4 * 4;
                float w0 = W1Tp[(jj + 0) * 64 + m];
                float w1 = W1Tp[(jj + 1) * 64 + m];
                float w2 = W1Tp[(jj + 2) * 64 + m];
                float w3 = W1Tp[(jj + 3) * 64 + m];
                float4 u0 = a0[j4], u1 = a1[j4];
                p0 = fmaf(w0, u0.x, p0); q0 = fmaf(w0, u1.x, q0);
                p1 = fmaf(w1, u0.y, p1); q1 = fmaf(w1, u1.y, q1);
                p2 = fmaf(w2, u0.z, p2); q2 = fmaf(w2, u1.z, q2);
                p3 = fmaf(w3, u0.w, p3); q3 = fmaf(w3, u1.w, q3);
            }
            float g0 = (p0 + p1) + (p2 + p3);
            float g1 = (q0 + q1) + (q2 + q3);
            vB[part * 64 + m]       = g0;   // ccs dead after stage 3 sync
            vB[256 + part * 64 + m] = g1;
        }
        __syncthreads();
        // Only g[0..31] is needed by the solve; Hs2 has 32 rows (FIX: was tid<128/mm&63,
        // which overflowed Hs2 and corrupted sample 1's Hessian + vA).
        if (tid < 64) {
            int ns = tid >> 5, mm = tid & 31;
            const float* gp = vB + ns * 256;
            Hs2[ns * 2080 + mm * 65 + 64] += gp[mm] + gp[64 + mm] + gp[128 + mm] + gp[192 + mm];
        }

        // ---- Stage 5+H2 fused per n-chunk of 128 (TENSOR) ----
        const int mb2 = wid * 16;          // m' tile (m' = sample*64 + m)
        const int s5  = wid & 1;           // H-phase sample
        const int nH  = (wid >> 1) * 16;   // H-phase col group
        const float4* W2v  = (const float4*)W2;
        const float4* W1Tv = (const float4*)W1T;

        #pragma unroll 1
        for (int ktile = 0; ktile < 2; ktile++) {
            float acc[16][4];
            #pragma unroll
            for (int i = 0; i < 16; i++)
                #pragma unroll
                for (int j = 0; j < 4; j++) acc[i][j] = 0.f;

            #pragma unroll 1
            for (int jt = 0; jt < 256; jt += 16) {
                // stage A (both samples, scaled) and B (n-chunk of W2), tf32
                #pragma unroll
                for (int r = 0; r < 2; r++) {
                    int f = tid + r * 256;
                    int jl = f >> 5, m4 = f & 31;
                    int smp = m4 >> 4;
                    float4 v = W1Tv[(jt + jl) * 16 + (m4 & 15)];
                    float aw = vC[smp * 256 + jt + jl];
                    float4 o;
                    o.x = __uint_as_float(to_tf32(v.x * aw));
                    o.y = __uint_as_float(to_tf32(v.y * aw));
                    o.z = __uint_as_float(to_tf32(v.z * aw));
                    o.w = __uint_as_float(to_tf32(v.w * aw));
                    *(float4*)(Asj2 + jl * 136 + m4 * 4) = o;
                }
                #pragma unroll
                for (int r = 0; r < 2; r++) {
                    int f = tid + r * 256;
                    int jl = f >> 5, n4 = f & 31;
                    float4 v = W2v[(jt + jl) * 64 + ktile * 32 + n4];
                    float4 o;
                    o.x = __uint_as_float(to_tf32(v.x));
                    o.y = __uint_as_float(to_tf32(v.y));
                    o.z = __uint_as_float(to_tf32(v.z));
                    o.w = __uint_as_float(to_tf32(v.w));
                    *(float4*)(W2s + jl * 136 + n4 * 4) = o;
                }
                __syncthreads();

                #pragma unroll
                for (int s = 0; s < 2; s++) {
                    int jb = s * 8;
                    const float* ar0 = Asj2 + (jb + t4) * 136;
                    const float* ar1 = Asj2 + (jb + t4 + 4) * 136;
                    uint32_t a0 = __float_as_uint(ar0[mb2 + g]);
                    uint32_t a1 = __float_as_uint(ar0[mb2 + g + 8]);
                    uint32_t a2 = __float_as_uint(ar1[mb2 + g]);
                    uint32_t a3 = __float_as_uint(ar1[mb2 + g + 8]);
                    const float* br0 = W2s + (jb + t4) * 136;
                    const float* br1 = W2s + (jb + t4 + 4) * 136;
                    #pragma unroll
                    for (int nt = 0; nt < 16; nt++) {
                        uint32_t b0 = __float_as_uint(br0[nt * 8 + g]);
                        uint32_t b1 = __float_as_uint(br1[nt * 8 + g]);
                        MMA_TF32(acc[nt], a0, a1, a2, a3, b0, b1);
                    }
                }
                __syncthreads();
            }

            // epilogue: Mt2[sample][n][m] (k-major per sample)
            {
                int smp = wid >> 2;
                int mloc = (wid & 3) * 16 + g;
                float* Mbase = Mt2 + smp * 8704;
                #pragma unroll
                for (int nt = 0; nt < 16; nt++) {
                    int n0 = nt * 8 + t4 * 2;
                    Mbase[n0 * 68 + mloc]           = acc[nt][0];
                    Mbase[(n0 + 1) * 68 + mloc]     = acc[nt][1];
                    Mbase[n0 * 68 + mloc + 8]       = acc[nt][2];
                    Mbase[(n0 + 1) * 68 + mloc + 8] = acc[nt][3];
                }
            }
            __syncthreads();

            // H2 over this k-chunk: Hs2[s5] += sum_k e_k M[k][32+i] M[k][j]
            {
                float hacc[2][2][4];
                #pragma unroll
                for (int a = 0; a < 2; a++)
                    #pragma unroll
                    for (int c = 0; c < 2; c++)
                        #pragma unroll
                        for (int d = 0; d < 4; d++) hacc[a][c][d] = 0.f;

                const float* eesN = vE + s5 * 256 + ktile * 128;
                #pragma unroll 2
                for (int kk = 0; kk < 128; kk += 8) {
                    const float* r0 = Mt2 + (s5 * 128 + kk + t4) * 68;
                    const float* r1 = r0 + 4 * 68;
                    float w0 = eesN[kk + t4];
                    float w1 = eesN[kk + t4 + 4];
                    uint32_t af[2][4];
                    #pragma unroll
                    for (int mi = 0; mi < 2; mi++) {
                        int mH = mi * 16;
                        af[mi][0] = to_tf32(r0[32 + mH + g] * w0);
                        af[mi][1] = to_tf32(r0[32 + mH + g + 8] * w0);
                        af[mi][2] = to_tf32(r1[32 + mH + g] * w1);
                        af[mi][3] = to_tf32(r1[32 + mH + g + 8] * w1);
                    }
                    #pragma unroll
                    for (int nt = 0; nt < 2; nt++) {
                        int nb = nH + nt * 8;
                        uint32_t b0 = to_tf32(r0[nb + g]);
                        uint32_t b1 = to_tf32(r1[nb + g]);
                        MMA_TF32(hacc[0][nt], af[0][0], af[0][1], af[0][2], af[0][3], b0, b1);
                        MMA_TF32(hacc[1][nt], af[1][0], af[1][1], af[1][2], af[1][3], b0, b1);
                    }
                }
                float* HsS = Hs2 + s5 * 2080;
                #pragma unroll
                for (int mi = 0; mi < 2; mi++)
                    #pragma unroll
                    for (int nt = 0; nt < 2; nt++) {
                        int j0 = nH + nt * 8 + t4 * 2;
                        int row = mi * 16 + g;
                        HsS[row * 65 + j0]           += hacc[mi][nt][0];
                        HsS[row * 65 + j0 + 1]       += hacc[mi][nt][1];
                        HsS[(row + 8) * 65 + j0]     += hacc[mi][nt][2];
                        HsS[(row + 8) * 65 + j0 + 1] += hacc[mi][nt][3];
                    }
            }
            __syncthreads();
        }

        // ---- H1 (TENSOR): Hs2[s] += sum_k d_k W1T[k][32+i] W1T[k][j] ----
        {
            float hacc[2][2][4];
            #pragma unroll
            for (int a = 0; a < 2; a++)
                #pragma unroll
                for (int c = 0; c < 2; c++)
                    #pragma unroll
                    for (int d = 0; d < 4; d++) hacc[a][c][d] = 0.f;

            const float* ddsN = vD + s5 * 256;
            #pragma unroll 1
            for (int kt = 0; kt < 256; kt += 16) {
                {
                    int kl = tid >> 4, m4 = tid & 15;
                    *(float4*)(Asj2 + kl * 136 + m4 * 4) = W1Tv[(kt + kl) * 16 + m4];
                }
                __syncthreads();
                #pragma unroll
                for (int s = 0; s < 2; s++) {
                    int kb = s * 8;
                    const float* r0 = Asj2 + (kb + t4) * 136;
                    const float* r1 = Asj2 + (kb + t4 + 4) * 136;
                    float w0 = ddsN[kt + kb + t4];
                    float w1 = ddsN[kt + kb + t4 + 4];
                    uint32_t af[2][4];
                    #pragma unroll
                    for (int mi = 0; mi < 2; mi++) {
                        int mH = mi * 16;
                        af[mi][0] = to_tf32(r0[32 + mH + g] * w0);
                        af[mi][1] = to_tf32(r0[32 + mH + g + 8] * w0);
                        af[mi][2] = to_tf32(r1[32 + mH + g] * w1);
                        af[mi][3] = to_tf32(r1[32 + mH + g + 8] * w1);
                    }
                    #pragma unroll
                    for (int nt = 0; nt < 2; nt++) {
                        int nb = nH + nt * 8;
                        uint32_t b0 = to_tf32(r0[nb + g]);
                        uint32_t b1 = to_tf32(r1[nb + g]);
                        MMA_TF32(hacc[0][nt], af[0][0], af[0][1], af[0][2], af[0][3], b0, b1);
                        MMA_TF32(hacc[1][nt], af[1][0], af[1][1], af[1][2], af[1][3], b0, b1);
                    }
                }
                __syncthreads();
            }
            float* HsS = Hs2 + s5 * 2080;
            #pragma unroll
            for (int mi = 0; mi < 2; mi++)
                #pragma unroll
                for (int nt = 0; nt < 2; nt++) {
                    int j0 = nH + nt * 8 + t4 * 2;
                    int row = mi * 16 + g;
                    HsS[row * 65 + j0]           += hacc[mi][nt][0];
                    HsS[row * 65 + j0 + 1]       += hacc[mi][nt][1];
                    HsS[(row + 8) * 65 + j0]     += hacc[mi][nt][2];
                    HsS[(row + 8) * 65 + j0 + 1] += hacc[mi][nt][3];
                }
        }
        __syncthreads();
    }

    // ---- Solve (2 warps, one per sample) ----
    float* Sv = Mt2;   // dead
    if (tid < 64) {
        int ws = tid >> 5, ln = tid & 31;
        const float* HsS = Hs2 + ws * 2080;
        float* SvN = Sv + ws * 1088;
        const float* qd = xs + ws * 64 + 32;
        float r = HsS[ln * 65 + 64];   // gsA
        #pragma unroll 8
        for (int j = 0; j < 32; j++) r -= HsS[ln * 65 + j] * qd[j];
        #pragma unroll 8
        for (int j = 0; j < 32; j++)
            SvN[ln * 34 + j] = HsS[ln * 65 + 32 + j] + ((ln == j) ? 2.0f : 0.0f);
        SvN[ln * 34 + 32] = r;
        __syncwarp();

        for (int p = 0; p < 32; p++) {
            float v = (ln >= p) ? fabsf(SvN[ln * 34 + p]) : -1.0f;
            int idx = ln;
            #pragma unroll
            for (int off = 16; off; off >>= 1) {
                float v2 = __shfl_xor_sync(0xffffffffu, v, off);
                int   i2 = __shfl_xor_sync(0xffffffffu, idx, off);
                if (v2 > v || (v2 == v && i2 < idx)) { v = v2; idx = i2; }
            }
            if (idx != p) {
                float t1 = SvN[p * 34 + ln];
                SvN[p * 34 + ln]   = SvN[idx * 34 + ln];
                SvN[idx * 34 + ln] = t1;
                if (ln == 0) {
                    float t2 = SvN[p * 34 + 32];
                    SvN[p * 34 + 32]   = SvN[idx * 34 + 32];
                    SvN[idx * 34 + 32] = t2;
                }
            }
            __syncwarp();
            float pinvv = 1.0f / SvN[p * 34 + p];
            if (ln != p) {
                float f = SvN[ln * 34 + p] * pinvv;
                for (int c = p; c < 33; c++)
                    SvN[ln * 34 + c] -= f * SvN[p * 34 + c];
            }
            __syncwarp();
        }
        float qdd = SvN[ln * 34 + 32] / SvN[ln * 34 + ln];
        int sample = b * 2 + ws;
        out[sample * 64 + ln]      = xs[ws * 64 + 32 + ln];
        out[sample * 64 + 32 + ln] = qdd;
    }
}

extern "C" void kernel_launch(void* const* d_in, const int* in_sizes, int n_in,
                              void* d_out, int out_size)
{
    const float* x   = (const float*)d_in[0];
    const float* W1m = (const float*)d_in[1];
    const float* b1m = (const float*)d_in[2];
    const float* W2m = (const float*)d_in[3];
    const float* b2m = (const float*)d_in[4];
    const float* W3m = (const float*)d_in[5];
    const float* W1q = (const float*)d_in[6];
    const float* b1q = (const float*)d_in[7];
    const float* W2q = (const float*)d_in[8];
    const float* b2q = (const float*)d_in[9];
    const float* W3q = (const float*)d_in[10];
    float* out = (float*)d_out;

    int B = in_sizes[0] / 64;

    prep_kernel<<<256, 256>>>(W1m, W2m, W1q, W2q);
    cudaFuncSetAttribute(lnn_kernel, cudaFuncAttributeMaxDynamicSharedMemorySize, SMEM_BYTES);
    lnn_kernel<<<B / 2, 256, SMEM_BYTES>>>(x, W1m, b1m, W2m, b2m, W3m,
                                           W1q, b1q, W2q, b2q, W3q, out);
}

// round 12
// speedup vs baseline: 2.5095x; 1.0556x over previous
#include <cuda_runtime.h>
#include <math.h>
#include <stdint.h>

#define HD 256
#define DD 64

__device__ float g_W1T[2 * DD * HD];   // [pass][(j*64 + m)]
__device__ float g_W2T[2 * HD * HD];   // [pass][(k*256 + j)]

__global__ void prep_kernel(const float* __restrict__ W1m, const float* __restrict__ W2m,
                            const float* __restrict__ W1q, const float* __restrict__ W2q)
{
    int t = blockIdx.x * blockDim.x + threadIdx.x;
    if (t < DD * HD) {
        int j = t >> 6, m = t & 63;
        g_W1T[t]           = W1m[m * HD + j];
        g_W1T[DD * HD + t] = W1q[m * HD + j];
    }
    if (t < HD * HD) {
        int k = t >> 8, j = t & 255;
        g_W2T[t]           = W2m[j * HD + k];
        g_W2T[HD * HD + t] = W2q[j * HD + k];
    }
}

__device__ __forceinline__ uint32_t to_tf32(float x) {
    uint32_t r;
    asm("cvt.rna.tf32.f32 %0, %1;" : "=r"(r) : "f"(x));
    return r;
}

#define MMA_TF32(acc, a0, a1, a2, a3, b0, b1)                                   \
    asm volatile(                                                               \
        "mma.sync.aligned.m16n8k8.row.col.f32.tf32.tf32.f32 "                   \
        "{%0,%1,%2,%3}, {%4,%5,%6,%7}, {%8,%9}, {%0,%1,%2,%3};\n"               \
        : "+f"(acc[0]), "+f"(acc[1]), "+f"(acc[2]), "+f"(acc[3])                \
        : "r"(a0), "r"(a1), "r"(a2), "r"(a3), "r"(b0), "r"(b1))

// Shared memory (floats), NS=2 samples per CTA:
//   Mt2  [2][128][68] 17408  M n-chunk for both samples (k-major); Sv in solve
//   W2s  [16][136]     2176  tf32 W2 (j x n-chunk) tile
//   Asj2 [16][136]     2176  tf32 scaled A tile (m' = 2x64); H1 W1T tile
//   Hs2  [2][32][65]   4160  H rows 32..63 per sample; col 64 = gsA (rows 0..31 only)
//   vA/vB/vC/vD/vE 512 each: h1->aus | ccs->gpart | aas | sss->dds | ees
//   xs 128
#define SMEM_FLOATS (17408 + 2176 + 2176 + 4160 + 5*512 + 128)
#define SMEM_BYTES  (SMEM_FLOATS * 4)

__global__ __launch_bounds__(256, 2)
void lnn_kernel(const float* __restrict__ x,
                const float* __restrict__ W1m, const float* __restrict__ b1m,
                const float* __restrict__ W2m, const float* __restrict__ b2m,
                const float* __restrict__ W3m,
                const float* __restrict__ W1q, const float* __restrict__ b1q,
                const float* __restrict__ W2q, const float* __restrict__ b2q,
                const float* __restrict__ W3q,
                float* __restrict__ out)
{
    extern __shared__ float sm[];
    float* Mt2  = sm;                // 17408
    float* W2s  = Mt2 + 17408;       // 2176 (pitch 136)
    float* Asj2 = W2s + 2176;        // 2176 (pitch 136)
    float* Hs2  = Asj2 + 2176;       // 4160 (pitch 65; col 64 = gsA)
    float* vA   = Hs2 + 4160;        // 512
    float* vB   = vA + 512;          // 512
    float* vC   = vB + 512;          // 512
    float* vD   = vC + 512;          // 512
    float* vE   = vD + 512;          // 512
    float* xs   = vE + 512;          // 128

    const int tid = threadIdx.x;
    const int b   = blockIdx.x;      // samples 2b, 2b+1

    for (int q = tid; q < 4160; q += 256) Hs2[q] = 0.0f;
    if (tid < 128) xs[tid] = x[b * 128 + tid];
    __syncthreads();

    const int wid = tid >> 5, lane = tid & 31;
    const int g = lane >> 2, t4 = lane & 3;

    #pragma unroll 1
    for (int pass = 0; pass < 2; pass++) {
        const float* W1  = pass ? W1q : W1m;
        const float* b1  = pass ? b1q : b1m;
        const float* W2  = pass ? W2q : W2m;
        const float* b2  = pass ? b2q : b2m;
        const float* W3  = pass ? W3q : W3m;
        const float* W1T = g_W1T + pass * (DD * HD);
        const float* W2T = g_W2T + pass * (HD * HD);

        // ---- Stage 1: z1 = x W1 + b1 (both samples); h1, a, s ----
        {
            int j = tid;
            float bv = b1[j];
            float p0 = bv, p1 = 0.f, p2 = 0.f, p3 = 0.f;
            float q0 = bv, q1 = 0.f, q2 = 0.f, q3 = 0.f;
            const float4* x0 = (const float4*)xs;
            const float4* x1 = (const float4*)(xs + 64);
            #pragma unroll 4
            for (int i4 = 0; i4 < 16; i4++) {
                int i = i4 * 4;
                float w0 = W1[(i + 0) * HD + j];
                float w1 = W1[(i + 1) * HD + j];
                float w2 = W1[(i + 2) * HD + j];
                float w3 = W1[(i + 3) * HD + j];
                float4 u0 = x0[i4], u1 = x1[i4];
                p0 = fmaf(u0.x, w0, p0); q0 = fmaf(u1.x, w0, q0);
                p1 = fmaf(u0.y, w1, p1); q1 = fmaf(u1.y, w1, q1);
                p2 = fmaf(u0.z, w2, p2); q2 = fmaf(u1.z, w2, q2);
                p3 = fmaf(u0.w, w3, p3); q3 = fmaf(u1.w, w3, q3);
            }
            float z0v = (p0 + p1) + (p2 + p3);
            float z1v = (q0 + q1) + (q2 + q3);
            #pragma unroll
            for (int ns = 0; ns < 2; ns++) {
                float z = ns ? z1v : z0v;
                float h, a, s;
                if (pass == 0) {
                    float sg = 1.0f / (1.0f + __expf(-z));
                    h = fmaxf(z, 0.0f) + log1pf(__expf(-fabsf(z)));
                    a = sg;
                    s = sg * (1.0f - sg);
                } else {
                    float t = tanhf(0.5f * z);
                    float o = 1.0f - t * t;
                    h = z * t;
                    a = fmaf(0.5f * z, o, t);
                    s = o * (1.0f - 0.5f * z * t);
                }
                vA[ns * 256 + j] = h;
                vC[ns * 256 + j] = a;
                vD[ns * 256 + j] = s;
            }
        }
        __syncthreads();

        // ---- Stage 2: z2 = h1 W2 + b2 ; c, e ----
        {
            int k = tid;
            float bv = b2[k];
            float p0 = bv, p1 = 0.f, p2 = 0.f, p3 = 0.f;
            float q0 = bv, q1 = 0.f, q2 = 0.f, q3 = 0.f;
            const float4* h0 = (const float4*)vA;
            const float4* h1v = (const float4*)(vA + 256);
            #pragma unroll 4
            for (int l4 = 0; l4 < 64; l4++) {
                int l = l4 * 4;
                float w0 = W2[(l + 0) * HD + k];
                float w1 = W2[(l + 1) * HD + k];
                float w2 = W2[(l + 2) * HD + k];
                float w3 = W2[(l + 3) * HD + k];
                float4 u0 = h0[l4], u1 = h1v[l4];
                p0 = fmaf(u0.x, w0, p0); q0 = fmaf(u1.x, w0, q0);
                p1 = fmaf(u0.y, w1, p1); q1 = fmaf(u1.y, w1, q1);
                p2 = fmaf(u0.z, w2, p2); q2 = fmaf(u1.z, w2, q2);
                p3 = fmaf(u0.w, w3, p3); q3 = fmaf(u1.w, w3, q3);
            }
            float z0v = (p0 + p1) + (p2 + p3);
            float z1v = (q0 + q1) + (q2 + q3);
            float w3v = W3[k];
            #pragma unroll
            for (int ns = 0; ns < 2; ns++) {
                float z = ns ? z1v : z0v;
                float a, s;
                if (pass == 0) {
                    float sg = 1.0f / (1.0f + __expf(-z));
                    a = sg;
                    s = sg * (1.0f - sg);
                } else {
                    float t = tanhf(0.5f * z);
                    float o = 1.0f - t * t;
                    a = fmaf(0.5f * z, o, t);
                    s = o * (1.0f - 0.5f * z * t);
                }
                vB[ns * 256 + k] = a * w3v;
                vE[ns * 256 + k] = s * w3v;
            }
        }
        __syncthreads();

        // ---- Stage 3: u = W2 c ; dds = s*u, aus = a*u ----
        {
            int j = tid;
            float p0 = 0.f, p1 = 0.f, p2 = 0.f, p3 = 0.f;
            float q0 = 0.f, q1 = 0.f, q2 = 0.f, q3 = 0.f;
            const float4* c0 = (const float4*)vB;
            const float4* c1 = (const float4*)(vB + 256);
            #pragma unroll 4
            for (int k4 = 0; k4 < 64; k4++) {
                int k = k4 * 4;
                float w0 = W2T[(k + 0) * HD + j];
                float w1 = W2T[(k + 1) * HD + j];
                float w2 = W2T[(k + 2) * HD + j];
                float w3 = W2T[(k + 3) * HD + j];
                float4 u0 = c0[k4], u1 = c1[k4];
                p0 = fmaf(u0.x, w0, p0); q0 = fmaf(u1.x, w0, q0);
                p1 = fmaf(u0.y, w1, p1); q1 = fmaf(u1.y, w1, q1);
                p2 = fmaf(u0.z, w2, p2); q2 = fmaf(u1.z, w2, q2);
                p3 = fmaf(u0.w, w3, p3); q3 = fmaf(u1.w, w3, q3);
            }
            float u0v = (p0 + p1) + (p2 + p3);
            float u1v = (q0 + q1) + (q2 + q3);
            float s0 = vD[j], s1 = vD[256 + j];
            float a0 = vC[j], a1 = vC[256 + j];
            vD[j]       = s0 * u0v;  vD[256 + j] = s1 * u1v;
            vA[j]       = a0 * u0v;  vA[256 + j] = a1 * u1v;
        }
        __syncthreads();

        // ---- Stage 4: g = W1 (a*u), 4-way j-split, both samples ----
        {
            int m = tid & 63, part = tid >> 6;
            const float* W1Tp = W1T + part * 64 * 64;
            const float4* a0 = (const float4*)(vA + part * 64);
            const float4* a1 = (const float4*)(vA + 256 + part * 64);
            float p0 = 0.f, p1 = 0.f, p2 = 0.f, p3 = 0.f;
            float q0 = 0.f, q1 = 0.f, q2 = 0.f, q3 = 0.f;
            #pragma unroll 4
            for (int j4 = 0; j4 < 16; j4++) {
                int jj = j4 * 4;
                float w0 = W1Tp[(jj + 0) * 64 + m];
                float w1 = W1Tp[(jj + 1) * 64 + m];
                float w2 = W1Tp[(jj + 2) * 64 + m];
                float w3 = W1Tp[(jj + 3) * 64 + m];
                float4 u0 = a0[j4], u1 = a1[j4];
                p0 = fmaf(w0, u0.x, p0); q0 = fmaf(w0, u1.x, q0);
                p1 = fmaf(w1, u0.y, p1); q1 = fmaf(w1, u1.y, q1);
                p2 = fmaf(w2, u0.z, p2); q2 = fmaf(w2, u1.z, q2);
                p3 = fmaf(w3, u0.w, p3); q3 = fmaf(w3, u1.w, q3);
            }
            float g0 = (p0 + p1) + (p2 + p3);
            float g1 = (q0 + q1) + (q2 + q3);
            vB[part * 64 + m]       = g0;   // ccs dead after stage 3 sync
            vB[256 + part * 64 + m] = g1;
        }
        __syncthreads();
        // Only g[0..31] feeds the solve; Hs2 has 32 rows per sample.
        if (tid < 64) {
            int ns = tid >> 5, mm = tid & 31;
            const float* gp = vB + ns * 256;
            Hs2[ns * 2080 + mm * 65 + 64] += gp[mm] + gp[64 + mm] + gp[128 + mm] + gp[192 + mm];
        }

        // ---- Stage 5+H2 fused per n-chunk of 128 (TENSOR) ----
        // Warp tiling 2m x 8n: warp = (m-pair mp, n-half nh). B frag feeds 2 mma.
        const int mp  = wid & 3;           // m rows mp*32 .. mp*32+31 (m' = 2x64)
        const int nh  = wid >> 2;          // n cols nh*64 .. +63 (8 n-tiles)
        const int s5  = wid & 1;           // H-phase sample
        const int nH  = (wid >> 1) * 16;   // H-phase col group
        const float4* W2v  = (const float4*)W2;
        const float4* W1Tv = (const float4*)W1T;

        #pragma unroll 1
        for (int ktile = 0; ktile < 2; ktile++) {
            float acc[2][8][4];
            #pragma unroll
            for (int mi = 0; mi < 2; mi++)
                #pragma unroll
                for (int i = 0; i < 8; i++)
                    #pragma unroll
                    for (int j = 0; j < 4; j++) acc[mi][i][j] = 0.f;

            #pragma unroll 1
            for (int jt = 0; jt < 256; jt += 16) {
                // stage A (both samples, scaled) and B (n-chunk of W2), tf32
                #pragma unroll
                for (int r = 0; r < 2; r++) {
                    int f = tid + r * 256;
                    int jl = f >> 5, m4 = f & 31;
                    int smp = m4 >> 4;
                    float4 v = W1Tv[(jt + jl) * 16 + (m4 & 15)];
                    float aw = vC[smp * 256 + jt + jl];
                    float4 o;
                    o.x = __uint_as_float(to_tf32(v.x * aw));
                    o.y = __uint_as_float(to_tf32(v.y * aw));
                    o.z = __uint_as_float(to_tf32(v.z * aw));
                    o.w = __uint_as_float(to_tf32(v.w * aw));
                    *(float4*)(Asj2 + jl * 136 + m4 * 4) = o;
                }
                #pragma unroll
                for (int r = 0; r < 2; r++) {
                    int f = tid + r * 256;
                    int jl = f >> 5, n4 = f & 31;
                    float4 v = W2v[(jt + jl) * 64 + ktile * 32 + n4];
                    float4 o;
                    o.x = __uint_as_float(to_tf32(v.x));
                    o.y = __uint_as_float(to_tf32(v.y));
                    o.z = __uint_as_float(to_tf32(v.z));
                    o.w = __uint_as_float(to_tf32(v.w));
                    *(float4*)(W2s + jl * 136 + n4 * 4) = o;
                }
                __syncthreads();

                #pragma unroll
                for (int s = 0; s < 2; s++) {
                    int jb = s * 8;
                    const float* ar0 = Asj2 + (jb + t4) * 136;
                    const float* ar1 = Asj2 + (jb + t4 + 4) * 136;
                    uint32_t af[2][4];
                    #pragma unroll
                    for (int mi = 0; mi < 2; mi++) {
                        int mb = mp * 32 + mi * 16;
                        af[mi][0] = __float_as_uint(ar0[mb + g]);
                        af[mi][1] = __float_as_uint(ar0[mb + g + 8]);
                        af[mi][2] = __float_as_uint(ar1[mb + g]);
                        af[mi][3] = __float_as_uint(ar1[mb + g + 8]);
                    }
                    const float* br0 = W2s + (jb + t4) * 136;
                    const float* br1 = W2s + (jb + t4 + 4) * 136;
                    #pragma unroll
                    for (int nt = 0; nt < 8; nt++) {
                        int nb = nh * 64 + nt * 8;
                        uint32_t b0 = __float_as_uint(br0[nb + g]);
                        uint32_t b1 = __float_as_uint(br1[nb + g]);
                        MMA_TF32(acc[0][nt], af[0][0], af[0][1], af[0][2], af[0][3], b0, b1);
                        MMA_TF32(acc[1][nt], af[1][0], af[1][1], af[1][2], af[1][3], b0, b1);
                    }
                }
                __syncthreads();
            }

            // epilogue: Mt2[sample][n][m] (k-major per sample)
            {
                int smp = mp >> 1;
                float* Mbase = Mt2 + smp * 8704;
                #pragma unroll
                for (int mi = 0; mi < 2; mi++) {
                    int mloc = (mp & 1) * 32 + mi * 16 + g;
                    #pragma unroll
                    for (int nt = 0; nt < 8; nt++) {
                        int n0 = nh * 64 + nt * 8 + t4 * 2;
                        Mbase[n0 * 68 + mloc]           = acc[mi][nt][0];
                        Mbase[(n0 + 1) * 68 + mloc]     = acc[mi][nt][1];
                        Mbase[n0 * 68 + mloc + 8]       = acc[mi][nt][2];
                        Mbase[(n0 + 1) * 68 + mloc + 8] = acc[mi][nt][3];
                    }
                }
            }
            __syncthreads();

            // H2 over this k-chunk: Hs2[s5] += sum_k e_k M[k][32+i] M[k][j]
            {
                float hacc[2][2][4];
                #pragma unroll
                for (int a = 0; a < 2; a++)
                    #pragma unroll
                    for (int c = 0; c < 2; c++)
                        #pragma unroll
                        for (int d = 0; d < 4; d++) hacc[a][c][d] = 0.f;

                const float* eesN = vE + s5 * 256 + ktile * 128;
                #pragma unroll 2
                for (int kk = 0; kk < 128; kk += 8) {
                    const float* r0 = Mt2 + (s5 * 128 + kk + t4) * 68;
                    const float* r1 = r0 + 4 * 68;
                    float w0 = eesN[kk + t4];
                    float w1 = eesN[kk + t4 + 4];
                    uint32_t af[2][4];
                    #pragma unroll
                    for (int mi = 0; mi < 2; mi++) {
                        int mH = mi * 16;
                        af[mi][0] = to_tf32(r0[32 + mH + g] * w0);
                        af[mi][1] = to_tf32(r0[32 + mH + g + 8] * w0);
                        af[mi][2] = to_tf32(r1[32 + mH + g] * w1);
                        af[mi][3] = to_tf32(r1[32 + mH + g + 8] * w1);
                    }
                    #pragma unroll
                    for (int nt = 0; nt < 2; nt++) {
                        int nb = nH + nt * 8;
                        uint32_t b0 = to_tf32(r0[nb + g]);
                        uint32_t b1 = to_tf32(r1[nb + g]);
                        MMA_TF32(hacc[0][nt], af[0][0], af[0][1], af[0][2], af[0][3], b0, b1);
                        MMA_TF32(hacc[1][nt], af[1][0], af[1][1], af[1][2], af[1][3], b0, b1);
                    }
                }
                float* HsS = Hs2 + s5 * 2080;
                #pragma unroll
                for (int mi = 0; mi < 2; mi++)
                    #pragma unroll
                    for (int nt = 0; nt < 2; nt++) {
                        int j0 = nH + nt * 8 + t4 * 2;
                        int row = mi * 16 + g;
                        HsS[row * 65 + j0]           += hacc[mi][nt][0];
                        HsS[row * 65 + j0 + 1]       += hacc[mi][nt][1];
                        HsS[(row + 8) * 65 + j0]     += hacc[mi][nt][2];
                        HsS[(row + 8) * 65 + j0 + 1] += hacc[mi][nt][3];
                    }
            }
            __syncthreads();
        }

        // ---- H1 (TENSOR): Hs2[s] += sum_k d_k W1T[k][32+i] W1T[k][j] ----
        {
            float hacc[2][2][4];
            #pragma unroll
            for (int a = 0; a < 2; a++)
                #pragma unroll
                for (int c = 0; c < 2; c++)
                    #pragma unroll
                    for (int d = 0; d < 4; d++) hacc[a][c][d] = 0.f;

            const float* ddsN = vD + s5 * 256;
            #pragma unroll 1
            for (int kt = 0; kt < 256; kt += 16) {
                {
                    int kl = tid >> 4, m4 = tid & 15;
                    *(float4*)(Asj2 + kl * 136 + m4 * 4) = W1Tv[(kt + kl) * 16 + m4];
                }
                __syncthreads();
                #pragma unroll
                for (int s = 0; s < 2; s++) {
                    int kb = s * 8;
                    const float* r0 = Asj2 + (kb + t4) * 136;
                    const float* r1 = Asj2 + (kb + t4 + 4) * 136;
                    float w0 = ddsN[kt + kb + t4];
                    float w1 = ddsN[kt + kb + t4 + 4];
                    uint32_t af[2][4];
                    #pragma unroll
                    for (int mi = 0; mi < 2; mi++) {
                        int mH = mi * 16;
                        af[mi][0] = to_tf32(r0[32 + mH + g] * w0);
                        af[mi][1] = to_tf32(r0[32 + mH + g + 8] * w0);
                        af[mi][2] = to_tf32(r1[32 + mH + g] * w1);
                        af[mi][3] = to_tf32(r1[32 + mH + g + 8] * w1);
                    }
                    #pragma unroll
                    for (int nt = 0; nt < 2; nt++) {
                        int nb = nH + nt * 8;
                        uint32_t b0 = to_tf32(r0[nb + g]);
                        uint32_t b1 = to_tf32(r1[nb + g]);
                        MMA_TF32(hacc[0][nt], af[0][0], af[0][1], af[0][2], af[0][3], b0, b1);
                        MMA_TF32(hacc[1][nt], af[1][0], af[1][1], af[1][2], af[1][3], b0, b1);
                    }
                }
                __syncthreads();
            }
            float* HsS = Hs2 + s5 * 2080;
            #pragma unroll
            for (int mi = 0; mi < 2; mi++)
                #pragma unroll
                for (int nt = 0; nt < 2; nt++) {
                    int j0 = nH + nt * 8 + t4 * 2;
                    int row = mi * 16 + g;
                    HsS[row * 65 + j0]           += hacc[mi][nt][0];
                    HsS[row * 65 + j0 + 1]       += hacc[mi][nt][1];
                    HsS[(row + 8) * 65 + j0]     += hacc[mi][nt][2];
                    HsS[(row + 8) * 65 + j0 + 1] += hacc[mi][nt][3];
                }
        }
        __syncthreads();
    }

    // ---- Solve (2 warps, one per sample) ----
    float* Sv = Mt2;   // dead
    if (tid < 64) {
        int ws = tid >> 5, ln = tid & 31;
        const float* HsS = Hs2 + ws * 2080;
        float* SvN = Sv + ws * 1088;
        const float* qd = xs + ws * 64 + 32;
        float r = HsS[ln * 65 + 64];   // gsA
        #pragma unroll 8
        for (int j = 0; j < 32; j++) r -= HsS[ln * 65 + j] * qd[j];
        #pragma unroll 8
        for (int j = 0; j < 32; j++)
            SvN[ln * 34 + j] = HsS[ln * 65 + 32 + j] + ((ln == j) ? 2.0f : 0.0f);
        SvN[ln * 34 + 32] = r;
        __syncwarp();

        for (int p = 0; p < 32; p++) {
            float v = (ln >= p) ? fabsf(SvN[ln * 34 + p]) : -1.0f;
            int idx = ln;
            #pragma unroll
            for (int off = 16; off; off >>= 1) {
                float v2 = __shfl_xor_sync(0xffffffffu, v, off);
                int   i2 = __shfl_xor_sync(0xffffffffu, idx, off);
                if (v2 > v || (v2 == v && i2 < idx)) { v = v2; idx = i2; }
            }
            if (idx != p) {
                float t1 = SvN[p * 34 + ln];
                SvN[p * 34 + ln]   = SvN[idx * 34 + ln];
                SvN[idx * 34 + ln] = t1;
                if (ln == 0) {
                    float t2 = SvN[p * 34 + 32];
                    SvN[p * 34 + 32]   = SvN[idx * 34 + 32];
                    SvN[idx * 34 + 32] = t2;
                }
            }
            __syncwarp();
            float pinvv = 1.0f / SvN[p * 34 + p];
            if (ln != p) {
                float f = SvN[ln * 34 + p] * pinvv;
                for (int c = p; c < 33; c++)
                    SvN[ln * 34 + c] -= f * SvN[p * 34 + c];
            }
            __syncwarp();
        }
        float qdd = SvN[ln * 34 + 32] / SvN[ln * 34 + ln];
        int sample = b * 2 + ws;
        out[sample * 64 + ln]      = xs[ws * 64 + 32 + ln];
        out[sample * 64 + 32 + ln] = qdd;
    }
}

extern "C" void kernel_launch(void* const* d_in, const int* in_sizes, int n_in,
                              void* d_out, int out_size)
{
    const float* x   = (const float*)d_in[0];
    const float* W1m = (const float*)d_in[1];
    const float* b1m = (const float*)d_in[2];
    const float* W2m = (const float*)d_in[3];
    const float* b2m = (const float*)d_in[4];
    const float* W3m = (const float*)d_in[5];
    const float* W1q = (const float*)d_in[6];
    const float* b1q = (const float*)d_in[7];
    const float* W2q = (const float*)d_in[8];
    const float* b2q = (const float*)d_in[9];
    const float* W3q = (const float*)d_in[10];
    float* out = (float*)d_out;

    int B = in_sizes[0] / 64;

    prep_kernel<<<256, 256>>>(W1m, W2m, W1q, W2q);
    cudaFuncSetAttribute(lnn_kernel, cudaFuncAttributeMaxDynamicSharedMemorySize, SMEM_BYTES);
    lnn_kernel<<<B / 2, 256, SMEM_BYTES>>>(x, W1m, b1m, W2m, b2m, W3m,
                                           W1q, b1q, W2q, b2q, W3q, out);
}